// round 14
// baseline (speedup 1.0000x reference)
#include <cuda_runtime.h>
#include <cuda_fp16.h>
#include <cstdint>
#include <cstddef>

#define BR    4096
#define MF    20000
#define EMB   100
#define WROWS 104
#define KC    32
#define KSPL  4
#define EPSB  1e-5f
#define STG   22528         // A(p0) 4K | A(p1) 4K | Wh 7K | Wl 7K
#define NSTG  4
#define WSC   64.0f

typedef unsigned long long u64;
typedef unsigned int u32;

// ---------------- device scratch ----------------
__device__ int   g_mode;                       // 0=int32, 1=byte bool, 2=float32
__device__ unsigned short g_Wh[WROWS * MF];
__device__ unsigned short g_Wl[WROWS * MF];
__device__ float g_Part[KSPL][2][BR][104];
__device__ float g_H1[2 * BR * EMB];
__device__ float g_H2[2 * BR * EMB];
__device__ float g_H3[2 * BR * EMB];
__device__ float g_P[3][2][128][2][EMB];       // stage, pass, tile, {sum,sumsq}, col
__device__ float g_scb[3][2][2][EMB];          // stage, pass, {scale,shift}, col
__device__ int   g_cnt_tile[64];
__device__ int   g_cnt_merge;
__device__ int   g_cnt_small[2];

// ---------------- helpers ----------------
__device__ __forceinline__ u32 smem_u32(const void* p) {
    u32 a; asm("{ .reg .u64 t; cvta.to.shared.u64 t, %1; cvt.u32.u64 %0, t; }" : "=r"(a) : "l"(p));
    return a;
}
__device__ __forceinline__ void ldsm4(u32& r0, u32& r1, u32& r2, u32& r3, u32 addr) {
    asm volatile("ldmatrix.sync.aligned.m8n8.x4.shared.b16 {%0,%1,%2,%3}, [%4];"
        : "=r"(r0), "=r"(r1), "=r"(r2), "=r"(r3) : "r"(addr));
}
__device__ __forceinline__ void mma16816(float* d, const u32* a, const u32* b) {
    asm volatile("mma.sync.aligned.m16n8k16.row.col.f32.f16.f16.f32 "
        "{%0,%1,%2,%3}, {%4,%5,%6,%7}, {%8,%9}, {%0,%1,%2,%3};"
        : "+f"(d[0]), "+f"(d[1]), "+f"(d[2]), "+f"(d[3])
        : "r"(a[0]), "r"(a[1]), "r"(a[2]), "r"(a[3]), "r"(b[0]), "r"(b[1]));
}
__device__ __forceinline__ void cp16(u32 dst, const void* src) {
    asm volatile("cp.async.cg.shared.global [%0], [%1], 16;"
        :: "r"(dst), "l"(src) : "memory");
}
#define CP_COMMIT() asm volatile("cp.async.commit_group;" ::: "memory")
#define CP_WAIT1()  asm volatile("cp.async.wait_group 1;" ::: "memory")

__device__ __forceinline__ u32 sw64(u32 row, u32 colb) {
    return row * 64 + (colb ^ (((row >> 1) & 3) << 4));
}
__device__ __forceinline__ u32 pk_f16(float lo, float hi) {
    u32 r; asm("cvt.rn.f16x2.f32 %0, %1, %2;" : "=r"(r) : "f"(hi), "f"(lo));
    return r;
}
__device__ __forceinline__ u64 pk2(float lo, float hi) {
    u64 d; asm("mov.b64 %0, {%1, %2};" : "=l"(d) : "f"(lo), "f"(hi)); return d;
}
__device__ __forceinline__ u64 fma2(u64 a, u64 b, u64 c) {
    u64 d; asm("fma.rn.f32x2 %0, %1, %2, %3;" : "=l"(d) : "l"(a), "l"(b), "l"(c)); return d;
}
__device__ __forceinline__ float2 upk2(u64 v) {
    float2 r; asm("mov.b64 {%0, %1}, %2;" : "=f"(r.x), "=f"(r.y) : "l"(v)); return r;
}

// ---------------- mask dtype classifier + counter reset ----------------
__global__ void k_detect(const unsigned char* __restrict__ m) {
    __shared__ int s_nz, s_gt;
    if (threadIdx.x < 64) g_cnt_tile[threadIdx.x] = 0;
    if (threadIdx.x == 64) g_cnt_merge = 0;
    if (threadIdx.x == 65) g_cnt_small[0] = 0;
    if (threadIdx.x == 66) g_cnt_small[1] = 0;
    if (threadIdx.x == 0) { s_nz = 0; s_gt = 0; }
    __syncthreads();
    int nz = 0, gt = 0;
    for (int i = threadIdx.x; i < 65536; i += blockDim.x) {
        unsigned char v = m[i];
        nz += (v != 0); gt += (v > 1);
    }
    atomicAdd(&s_nz, nz); atomicAdd(&s_gt, gt);
    __syncthreads();
    if (threadIdx.x == 0)
        g_mode = (s_gt > 64) ? 2 : (s_nz > 24576) ? 1 : 0;
}

// ---------------- W split precompute ----------------
__global__ void k_wcvt(const float* __restrict__ w, int base) {
    int i = base + blockIdx.x * blockDim.x + threadIdx.x;
    if (i >= WROWS * MF / 2) return;
    int row = i / (MF / 2), within = i % (MF / 2);
    if (row < EMB) {
        float2 v = *(const float2*)(w + (size_t)row * MF + 2 * within);
        float sx = WSC * v.x, sy = WSC * v.y;
        float hx = __half2float(__float2half_rn(sx));
        float hy = __half2float(__float2half_rn(sy));
        ((u32*)g_Wh)[i] = pk_f16(hx, hy);
        ((u32*)g_Wl)[i] = pk_f16(sx - hx, sy - hy);
    } else {
        ((u32*)g_Wh)[i] = 0u;
        ((u32*)g_Wl)[i] = 0u;
    }
}

// ---------------- Layer 1: 2-term fp16 mma.sync + fused merge/stats --------
// grid = 256: tile = bid>>2 (64 rows), ks = bid&3 (157/156/156/156 chunks).
// Stage (22528B): A(p0)@0 4K | A(p1)@4096 4K | Wh@8192 7K | Wl@15360 7K.
__global__ __launch_bounds__(256, 2)
void k_big(const float* __restrict__ x, const void* __restrict__ mk,
           const float* __restrict__ xr, const float* __restrict__ bias,
           const float* __restrict__ gamma, const float* __restrict__ beta)
{
    extern __shared__ char smem[];
    const u32 sb = smem_u32(smem);
    const int t = threadIdx.x;
    const int w = t >> 5, lane = t & 31;
    const int tile = blockIdx.x >> 2, ks = blockIdx.x & 3;
    const int r0g = tile * 64;
    const int ci0 = ks ? (157 + 156 * (ks - 1)) : 0;
    const int n   = ks ? 156 : 157;
    const size_t k0g = (size_t)ci0 * KC;
    const int pa = w >> 2, nc = w & 3;
    const int mode = g_mode;

    const int arow = t >> 2, seg = t & 3;
    const size_t abase = (size_t)(r0g + arow) * MF + k0g + (size_t)seg * 8;
    const u32 aoff = sw64(arow, seg * 16);

    const int gi1 = t + 256;
    const bool w1v = (gi1 < 416);
    const int wr0 = t >> 2, wsg0 = t & 3;
    const int wr1 = gi1 >> 2, wsg1 = gi1 & 3;
    const u32 woff0 = sw64(wr0, wsg0 * 16);
    const u32 woff1 = sw64(wr1, wsg1 * 16);
    const size_t wsrc0 = (size_t)wr0 * MF + k0g + (size_t)wsg0 * 8;
    const size_t wsrc1 = (size_t)wr1 * MF + k0g + (size_t)wsg1 * 8;

    float acc[4][4][4];
    #pragma unroll
    for (int mf = 0; mf < 4; mf++)
        #pragma unroll
        for (int nf = 0; nf < 4; nf++)
            #pragma unroll
            for (int e = 0; e < 4; e++) acc[mf][nf][e] = 0.f;

    // zero W pad rows 104..111 in all 4 stages
    {
        const int stg_i = t >> 6, rem = t & 63;
        const int mat = rem >> 5, rr = 104 + ((rem & 31) >> 2), s = rem & 3;
        *(uint4*)(smem + stg_i * STG + 8192 + mat * 7168 + sw64(rr, s * 16)) =
            make_uint4(0, 0, 0, 0);
    }

    auto CPW = [&](int j) {
        const u32 base = sb + (j & 3) * STG;
        const size_t ko = (size_t)j * KC;
        cp16(base +  8192 + woff0, g_Wh + wsrc0 + ko);
        cp16(base + 15360 + woff0, g_Wl + wsrc0 + ko);
        if (w1v) {
            cp16(base +  8192 + woff1, g_Wh + wsrc1 + ko);
            cp16(base + 15360 + woff1, g_Wl + wsrc1 + ko);
        }
    };

    auto STAGE = [&](int j) {
        const size_t g = abase + (size_t)j * KC;
        float v[8], vc[8];
        float4 x0 = *(const float4*)(x + g);
        float4 x1 = *(const float4*)(x + g + 4);
        v[0]=x0.x; v[1]=x0.y; v[2]=x0.z; v[3]=x0.w;
        v[4]=x1.x; v[5]=x1.y; v[6]=x1.z; v[7]=x1.w;
        float4 q0 = *(const float4*)(xr + g);
        float4 q1 = *(const float4*)(xr + g + 4);
        float q[8] = {q0.x,q0.y,q0.z,q0.w,q1.x,q1.y,q1.z,q1.w};
        if (mode == 1) {
            uint2 mm = *(const uint2*)((const unsigned char*)mk + g);
            u32 lo = mm.x, hi = mm.y;
            #pragma unroll
            for (int m = 0; m < 4; m++) {
                vc[m]   = ((lo >> (m*8)) & 0xff) ? q[m]   : v[m];
                vc[m+4] = ((hi >> (m*8)) & 0xff) ? q[m+4] : v[m+4];
            }
        } else if (mode == 0) {
            int4 m0 = *(const int4*)((const int*)mk + g);
            int4 m1 = *(const int4*)((const int*)mk + g + 4);
            int mi[8] = {m0.x,m0.y,m0.z,m0.w,m1.x,m1.y,m1.z,m1.w};
            #pragma unroll
            for (int m = 0; m < 8; m++) vc[m] = mi[m] ? q[m] : v[m];
        } else {
            float4 m0 = *(const float4*)((const float*)mk + g);
            float4 m1 = *(const float4*)((const float*)mk + g + 4);
            float mf_[8] = {m0.x,m0.y,m0.z,m0.w,m1.x,m1.y,m1.z,m1.w};
            #pragma unroll
            for (int m = 0; m < 8; m++) vc[m] = (mf_[m] != 0.f) ? q[m] : v[m];
        }
        uint4 HA0, HA1;
        HA0.x = pk_f16(v[0],v[1]);  HA0.y = pk_f16(v[2],v[3]);
        HA0.z = pk_f16(v[4],v[5]);  HA0.w = pk_f16(v[6],v[7]);
        HA1.x = pk_f16(vc[0],vc[1]); HA1.y = pk_f16(vc[2],vc[3]);
        HA1.z = pk_f16(vc[4],vc[5]); HA1.w = pk_f16(vc[6],vc[7]);
        char* bs = smem + (j & 3) * STG;
        *(uint4*)(bs +        aoff) = HA0;
        *(uint4*)(bs + 4096 + aoff) = HA1;
    };

    const u32 rA0 = lane & 15;
    const u32 c16A = ((lane >> 4) & 1) * 16;
    const u32 xrA0 = ((rA0 >> 1) & 3) << 4;
    const u32 nrow = nc * 32 + ((lane >> 4) & 1) * 8 + (lane & 7);
    const u32 c16B = ((lane >> 3) & 1) * 16;
    const u32 baseB0 = nrow * 64,        xrB0 = ((nrow >> 1) & 3) << 4;
    const u32 baseB1 = (nrow + 16) * 64, xrB1 = (((nrow + 16) >> 1) & 3) << 4;

    auto COMP = [&](int j) {
        const u32 bs = sb + (j & 3) * STG;
        const u32 Ab = bs + pa * 4096;
        const u32 Wh = bs + 8192, Wl = bs + 15360;
        #pragma unroll
        for (int kss = 0; kss < 2; kss++) {
            const u32 kb = kss * 32;
            const u32 ka = (kb + c16A) ^ xrA0;
            u32 aF[4][4];
            #pragma unroll
            for (int mf = 0; mf < 4; mf++)
                ldsm4(aF[mf][0], aF[mf][1], aF[mf][2], aF[mf][3],
                      Ab + rA0 * 64 + mf * 1024 + ka);
            if (nc < 3) {
                u32 bH[4][2], bL[4][2];
                ldsm4(bH[0][0], bH[0][1], bH[1][0], bH[1][1], Wh + baseB0 + ((kb + c16B) ^ xrB0));
                ldsm4(bH[2][0], bH[2][1], bH[3][0], bH[3][1], Wh + baseB1 + ((kb + c16B) ^ xrB1));
                ldsm4(bL[0][0], bL[0][1], bL[1][0], bL[1][1], Wl + baseB0 + ((kb + c16B) ^ xrB0));
                ldsm4(bL[2][0], bL[2][1], bL[3][0], bL[3][1], Wl + baseB1 + ((kb + c16B) ^ xrB1));
                #pragma unroll
                for (int mf = 0; mf < 4; mf++)
                    #pragma unroll
                    for (int nf = 0; nf < 4; nf++) {
                        mma16816(acc[mf][nf], aF[mf], bH[nf]);
                        mma16816(acc[mf][nf], aF[mf], bL[nf]);
                    }
            } else {
                u32 bH[2][2], bL[2][2];
                ldsm4(bH[0][0], bH[0][1], bH[1][0], bH[1][1], Wh + baseB0 + ((kb + c16B) ^ xrB0));
                ldsm4(bL[0][0], bL[0][1], bL[1][0], bL[1][1], Wl + baseB0 + ((kb + c16B) ^ xrB0));
                #pragma unroll
                for (int mf = 0; mf < 4; mf++)
                    #pragma unroll
                    for (int nf = 0; nf < 2; nf++) {
                        mma16816(acc[mf][nf], aF[mf], bH[nf]);
                        mma16816(acc[mf][nf], aF[mf], bL[nf]);
                    }
            }
        }
    };

    // prologue
    CPW(0); CP_COMMIT();
    CPW(1); CP_COMMIT();
    CPW(2); CP_COMMIT();
    STAGE(0);
    STAGE(1);
    CP_WAIT1();
    __syncthreads();

    int i = 0;
    for (; i + 1 < n; i += 2) {
        COMP(i);
        if (i + 2 < n) STAGE(i + 2);
        COMP(i + 1);
        if (i + 3 < n) STAGE(i + 3);
        if (i + 3 < n) CPW(i + 3);
        CP_COMMIT();
        if (i + 4 < n) CPW(i + 4);
        CP_COMMIT();
        CP_WAIT1();
        __syncthreads();
    }
    if (i < n) COMP(i);

    // epilogue: raw partials -> g_Part[ks][pa]
    float* Pp = &g_Part[ks][pa][0][0];
    const int gq = lane >> 2, tt = lane & 3;
    #pragma unroll
    for (int mf = 0; mf < 4; mf++)
        #pragma unroll
        for (int nf = 0; nf < 4; nf++) {
            const int col = nc * 32 + nf * 8 + 2 * tt;
            if (col < EMB) {
                const int ra = r0g + mf * 16 + gq;
                *(float2*)&Pp[(size_t)ra * 104 + col] =
                    make_float2(acc[mf][nf][0], acc[mf][nf][1]);
                *(float2*)&Pp[(size_t)(ra + 8) * 104 + col] =
                    make_float2(acc[mf][nf][2], acc[mf][nf][3]);
            }
        }
    __syncthreads();

    // ---- fused merge: last k_big CTA of this tile merges K-splits ----
    __shared__ int s_flag;
    if (t == 0) {
        __threadfence();
        s_flag = (atomicAdd(&g_cnt_tile[tile], 1) == KSPL - 1) ? 1 : 0;
    }
    __syncthreads();
    if (!s_flag) return;

    float* Ds = (float*)smem;   // [64][104], stages are dead now
    const int mr = t >> 2, mcg = t & 3;
    for (int p = 0; p < 2; p++) {
        const size_t row = (size_t)r0g + mr;
        #pragma unroll
        for (int j = 0; j < 25; j++) {
            const int c = mcg * 25 + j;
            float v = (g_Part[0][p][row][c] + g_Part[1][p][row][c]
                     + g_Part[2][p][row][c] + g_Part[3][p][row][c]) * (1.0f / WSC)
                     + bias[c];
            v = fmaxf(v, 0.f);
            g_H1[((size_t)p * BR + row) * EMB + c] = v;
            Ds[mr * 104 + c] = v;
        }
        __syncthreads();
        if (t < EMB) {
            float s = 0.f, s2 = 0.f;
            #pragma unroll 8
            for (int rr = 0; rr < 64; rr++) { float u = Ds[rr * 104 + t]; s += u; s2 += u * u; }
            g_P[0][p][tile][0][t] = s;
            g_P[0][p][tile][1][t] = s2;
        }
        __syncthreads();
    }

    // ---- last merger computes BN stage-0 scale/shift ----
    if (t == 0) {
        __threadfence();
        s_flag = (atomicAdd(&g_cnt_merge, 1) == 63) ? 1 : 0;
    }
    __syncthreads();
    if (!s_flag) return;
    if (t < 200) {
        const int p = t / 100, c = t % 100;
        float s = 0.f, s2 = 0.f;
        #pragma unroll 4
        for (int it = 0; it < 64; it++) {
            s  += g_P[0][p][it][0][c];
            s2 += g_P[0][p][it][1][c];
        }
        float mu  = s * (1.f / BR);
        float var = s2 * (1.f / BR) - mu * mu;
        float sv  = gamma[c] * rsqrtf(var + EPSB);
        g_scb[0][p][0][c] = sv;
        g_scb[0][p][1][c] = beta[c] - mu * sv;
    }
}

// ---------------- Layers 2-4: small GEMM; stats precomputed; last CTA -------
// computes next stage's BN scale/shift.
__global__ __launch_bounds__(256, 2)
void k_small(int layer, const float* __restrict__ W,
             const float* __restrict__ bias,
             const float* __restrict__ ngamma, const float* __restrict__ nbeta,
             float* __restrict__ dout)
{
    extern __shared__ float sm[];
    float* Hs  = sm;            // 100*33
    float* Ws  = sm + 3300;     // 100*132
    float* red = sm + 16500;    // 2048
    float* sc  = sm + 18548;
    float* sh  = sm + 18676;

    const int t = threadIdx.x, tile = blockIdx.x, p = blockIdx.y;
    const int r0 = tile * 32;
    const int ty = t >> 4, tx = t & 15;
    const float* Hin = (layer == 0) ? g_H1 : (layer == 1) ? g_H2 : g_H3;
    const bool rin = (layer == 2), rout = (layer == 0);

    if (t < EMB) {
        sc[t] = g_scb[layer][p][0][t];
        sh[t] = g_scb[layer][p][1][t];
    }
    __syncthreads();

    const float* Hp = Hin + (size_t)p * BR * EMB;
    for (int i = t; i < 32 * EMB; i += 256) {
        int row = i / EMB, k = i % EMB;
        float v = Hp[(size_t)(r0 + row) * EMB + k] * sc[k] + sh[k];
        if (rin) v = fmaxf(v, 0.f);
        Hs[k * 33 + row] = v;
    }
    for (int i = t; i < EMB * EMB; i += 256) {
        int nn = i / EMB, k = i % EMB;
        Ws[k * 132 + nn] = W[i];
    }
    for (int i = t; i < EMB * 28; i += 256) {
        int k = i / 28, nn = 100 + i % 28;
        Ws[k * 132 + nn] = 0.f;
    }
    __syncthreads();

    u64 acc[2][4];
    #pragma unroll
    for (int r = 0; r < 2; r++)
        #pragma unroll
        for (int c = 0; c < 4; c++) acc[r][c] = 0ull;

    #pragma unroll 4
    for (int k = 0; k < EMB; k++) {
        const float* ak = Hs + k * 33 + ty * 2;
        float a0 = ak[0], a1 = ak[1];
        const u64* wp = (const u64*)(Ws + k * 132 + tx * 8);
        u64 b0 = wp[0], b1 = wp[1], b2 = wp[2], b3 = wp[3];
        u64 A0 = pk2(a0, a0), A1 = pk2(a1, a1);
        acc[0][0]=fma2(A0,b0,acc[0][0]); acc[0][1]=fma2(A0,b1,acc[0][1]);
        acc[0][2]=fma2(A0,b2,acc[0][2]); acc[0][3]=fma2(A0,b3,acc[0][3]);
        acc[1][0]=fma2(A1,b0,acc[1][0]); acc[1][1]=fma2(A1,b1,acc[1][1]);
        acc[1][2]=fma2(A1,b2,acc[1][2]); acc[1][3]=fma2(A1,b3,acc[1][3]);
    }

    float* Hout = (layer == 0) ? g_H2 : g_H3;
    float vo[2][8];
    #pragma unroll
    for (int r = 0; r < 2; r++) {
        int row = r0 + ty * 2 + r;
        #pragma unroll
        for (int cp = 0; cp < 4; cp++) {
            float2 f = upk2(acc[r][cp]);
            #pragma unroll
            for (int hh = 0; hh < 2; hh++) {
                int col = tx * 8 + cp * 2 + hh;
                float v = (hh ? f.y : f.x) + (col < EMB ? bias[col] : 0.f);
                if (rout) v = fmaxf(v, 0.f);
                vo[r][cp * 2 + hh] = v;
                if (col < EMB) {
                    if (layer == 2) dout[((size_t)p * BR + row) * EMB + col] = v;
                    else            Hout[((size_t)p * BR + row) * EMB + col] = v;
                }
            }
        }
    }
    if (layer < 2) {
        #pragma unroll
        for (int c = 0; c < 8; c++)
            red[ty * 128 + tx * 8 + c] = vo[0][c] + vo[1][c];
        __syncthreads();
        if (t < 128) {
            float s = 0.f;
            #pragma unroll
            for (int g = 0; g < 16; g++) s += red[g * 128 + t];
            if (t < EMB) g_P[layer + 1][p][tile][0][t] = s;
        }
        __syncthreads();
        #pragma unroll
        for (int c = 0; c < 8; c++)
            red[ty * 128 + tx * 8 + c] = vo[0][c]*vo[0][c] + vo[1][c]*vo[1][c];
        __syncthreads();
        if (t < 128) {
            float s = 0.f;
            #pragma unroll
            for (int g = 0; g < 16; g++) s += red[g * 128 + t];
            if (t < EMB) g_P[layer + 1][p][tile][1][t] = s;
        }
        __syncthreads();

        // last CTA computes next stage's BN scale/shift
        __shared__ int s_last;
        if (t == 0) {
            __threadfence();
            s_last = (atomicAdd(&g_cnt_small[layer], 1) == 255) ? 1 : 0;
        }
        __syncthreads();
        if (s_last && t < 200) {
            const int pp = t / 100, c = t % 100;
            float s = 0.f, s2 = 0.f;
            #pragma unroll 4
            for (int it = 0; it < 128; it++) {
                s  += g_P[layer + 1][pp][it][0][c];
                s2 += g_P[layer + 1][pp][it][1][c];
            }
            float mu  = s * (1.f / BR);
            float var = s2 * (1.f / BR) - mu * mu;
            float sv  = ngamma[c] * rsqrtf(var + EPSB);
            g_scb[layer + 1][pp][0][c] = sv;
            g_scb[layer + 1][pp][1][c] = nbeta[c] - mu * sv;
        }
    }
}

// ---------------- launch ----------------
extern "C" void kernel_launch(void* const* d_in, const int* in_sizes, int n_in,
                              void* d_out, int out_size)
{
    const float* x   = (const float*)d_in[0];
    const void*  mk  = d_in[1];
    const float* xr  = (const float*)d_in[2];
    const float* w1  = (const float*)d_in[3];
    const float* b1  = (const float*)d_in[4];
    const float* g1  = (const float*)d_in[5];
    const float* be1 = (const float*)d_in[6];
    const float* w2  = (const float*)d_in[7];
    const float* b2  = (const float*)d_in[8];
    const float* g2  = (const float*)d_in[9];
    const float* be2 = (const float*)d_in[10];
    const float* hw1 = (const float*)d_in[11];
    const float* hb1 = (const float*)d_in[12];
    const float* hg1 = (const float*)d_in[13];
    const float* hbe1= (const float*)d_in[14];
    const float* hw2 = (const float*)d_in[15];
    const float* hb2 = (const float*)d_in[16];
    float* out = (float*)d_out;

    cudaFuncSetAttribute(k_big,   cudaFuncAttributeMaxDynamicSharedMemorySize, NSTG * STG);
    cudaFuncSetAttribute(k_small, cudaFuncAttributeMaxDynamicSharedMemorySize, 76816);

    const int H = WROWS * MF / 2 / 2;
    k_detect<<<1, 256>>>((const unsigned char*)mk);                     // 1
    k_wcvt<<<(H + 255) / 256, 256>>>(w1, 0);                            // 2
    k_wcvt<<<(H + 255) / 256, 256>>>(w1, H);                            // 3
    k_big<<<256, 256, NSTG * STG>>>(x, mk, xr, b1, g1, be1);            // 4 <- profiled
    k_small<<<dim3(128, 2), 256, 76816>>>(0, w2, b2, g2, be2, nullptr); // 5
    k_small<<<dim3(128, 2), 256, 76816>>>(1, hw1, hb1, hg1, hbe1, nullptr);
    k_small<<<dim3(128, 2), 256, 76816>>>(2, hw2, hb2, hg1, hbe1, out);
}

// round 15
// speedup vs baseline: 1.1231x; 1.1231x over previous
#include <cuda_runtime.h>
#include <cuda_fp16.h>
#include <cstdint>
#include <cstddef>

#define BR    4096
#define MF    20000
#define EMB   100
#define WROWS 104
#define KC    32
#define KSPL  4
#define EPSB  1e-5f
#define STG   22528         // A(p0) 4K | A(p1) 4K | Wh 7K | Wl 7K
#define NSTG  4
#define WSC   64.0f

typedef unsigned long long u64;
typedef unsigned int u32;

// ---------------- device scratch ----------------
__device__ int   g_mode;
__device__ unsigned short g_Wh[WROWS * MF];
__device__ unsigned short g_Wl[WROWS * MF];
__device__ float g_Part[KSPL][2][BR][104];
__device__ float g_H1[2 * BR * EMB];
__device__ float g_H2[2 * BR * EMB];
__device__ float g_H3[2 * BR * EMB];
__device__ float g_P[3][2][128][2][EMB];       // stage, pass, tile, {sum,sumsq}, col
__device__ float g_scb[3][2][2][EMB];          // stage, pass, {scale,shift}, col
__device__ int   g_cnt[3];
__device__ int   g_flag[3];

// ---------------- helpers ----------------
__device__ __forceinline__ u32 smem_u32(const void* p) {
    u32 a; asm("{ .reg .u64 t; cvta.to.shared.u64 t, %1; cvt.u32.u64 %0, t; }" : "=r"(a) : "l"(p));
    return a;
}
__device__ __forceinline__ void ldsm4(u32& r0, u32& r1, u32& r2, u32& r3, u32 addr) {
    asm volatile("ldmatrix.sync.aligned.m8n8.x4.shared.b16 {%0,%1,%2,%3}, [%4];"
        : "=r"(r0), "=r"(r1), "=r"(r2), "=r"(r3) : "r"(addr));
}
__device__ __forceinline__ void mma16816(float* d, const u32* a, const u32* b) {
    asm volatile("mma.sync.aligned.m16n8k16.row.col.f32.f16.f16.f32 "
        "{%0,%1,%2,%3}, {%4,%5,%6,%7}, {%8,%9}, {%0,%1,%2,%3};"
        : "+f"(d[0]), "+f"(d[1]), "+f"(d[2]), "+f"(d[3])
        : "r"(a[0]), "r"(a[1]), "r"(a[2]), "r"(a[3]), "r"(b[0]), "r"(b[1]));
}
__device__ __forceinline__ void cp16(u32 dst, const void* src) {
    asm volatile("cp.async.cg.shared.global [%0], [%1], 16;"
        :: "r"(dst), "l"(src) : "memory");
}
#define CP_COMMIT() asm volatile("cp.async.commit_group;" ::: "memory")
#define CP_WAIT1()  asm volatile("cp.async.wait_group 1;" ::: "memory")

__device__ __forceinline__ u32 sw64(u32 row, u32 colb) {
    return row * 64 + (colb ^ (((row >> 1) & 3) << 4));
}
__device__ __forceinline__ u32 pk_f16(float lo, float hi) {
    u32 r; asm("cvt.rn.f16x2.f32 %0, %1, %2;" : "=r"(r) : "f"(hi), "f"(lo));
    return r;
}
__device__ __forceinline__ u64 pk2(float lo, float hi) {
    u64 d; asm("mov.b64 %0, {%1, %2};" : "=l"(d) : "f"(lo), "f"(hi)); return d;
}
__device__ __forceinline__ u64 fma2(u64 a, u64 b, u64 c) {
    u64 d; asm("fma.rn.f32x2 %0, %1, %2, %3;" : "=l"(d) : "l"(a), "l"(b), "l"(c)); return d;
}
__device__ __forceinline__ float2 upk2(u64 v) {
    float2 r; asm("mov.b64 {%0, %1}, %2;" : "=f"(r.x), "=f"(r.y) : "l"(v)); return r;
}

// ---------------- mask dtype classifier + counter reset ----------------
__global__ void k_detect(const unsigned char* __restrict__ m) {
    __shared__ int s_nz, s_gt;
    if (threadIdx.x < 3) { g_cnt[threadIdx.x] = 0; g_flag[threadIdx.x] = 0; }
    if (threadIdx.x == 0) { s_nz = 0; s_gt = 0; }
    __syncthreads();
    int nz = 0, gt = 0;
    for (int i = threadIdx.x; i < 65536; i += blockDim.x) {
        unsigned char v = m[i];
        nz += (v != 0); gt += (v > 1);
    }
    atomicAdd(&s_nz, nz); atomicAdd(&s_gt, gt);
    __syncthreads();
    if (threadIdx.x == 0)
        g_mode = (s_gt > 64) ? 2 : (s_nz > 24576) ? 1 : 0;
}

// ---------------- W split precompute ----------------
__global__ void k_wcvt(const float* __restrict__ w, int base) {
    int i = base + blockIdx.x * blockDim.x + threadIdx.x;
    if (i >= WROWS * MF / 2) return;
    int row = i / (MF / 2), within = i % (MF / 2);
    if (row < EMB) {
        float2 v = *(const float2*)(w + (size_t)row * MF + 2 * within);
        float sx = WSC * v.x, sy = WSC * v.y;
        float hx = __half2float(__float2half_rn(sx));
        float hy = __half2float(__float2half_rn(sy));
        ((u32*)g_Wh)[i] = pk_f16(hx, hy);
        ((u32*)g_Wl)[i] = pk_f16(sx - hx, sy - hy);
    } else {
        ((u32*)g_Wh)[i] = 0u;
        ((u32*)g_Wl)[i] = 0u;
    }
}

// ---------------- Layer 1: 2-term fp16 mma.sync (R13 verbatim) -------------
__global__ __launch_bounds__(256, 2)
void k_big(const float* __restrict__ x, const void* __restrict__ mk,
           const float* __restrict__ xr)
{
    extern __shared__ char smem[];
    const u32 sb = smem_u32(smem);
    const int t = threadIdx.x;
    const int w = t >> 5, lane = t & 31;
    const int tile = blockIdx.x >> 2, ks = blockIdx.x & 3;
    const int r0g = tile * 64;
    const int ci0 = ks ? (157 + 156 * (ks - 1)) : 0;
    const int n   = ks ? 156 : 157;
    const size_t k0g = (size_t)ci0 * KC;
    const int pa = w >> 2, nc = w & 3;
    const int mode = g_mode;

    const int arow = t >> 2, seg = t & 3;
    const size_t abase = (size_t)(r0g + arow) * MF + k0g + (size_t)seg * 8;
    const u32 aoff = sw64(arow, seg * 16);

    const int gi1 = t + 256;
    const bool w1v = (gi1 < 416);
    const int wr0 = t >> 2, wsg0 = t & 3;
    const int wr1 = gi1 >> 2, wsg1 = gi1 & 3;
    const u32 woff0 = sw64(wr0, wsg0 * 16);
    const u32 woff1 = sw64(wr1, wsg1 * 16);
    const size_t wsrc0 = (size_t)wr0 * MF + k0g + (size_t)wsg0 * 8;
    const size_t wsrc1 = (size_t)wr1 * MF + k0g + (size_t)wsg1 * 8;

    float acc[4][4][4];
    #pragma unroll
    for (int mf = 0; mf < 4; mf++)
        #pragma unroll
        for (int nf = 0; nf < 4; nf++)
            #pragma unroll
            for (int e = 0; e < 4; e++) acc[mf][nf][e] = 0.f;

    {
        const int stg_i = t >> 6, rem = t & 63;
        const int mat = rem >> 5, rr = 104 + ((rem & 31) >> 2), s = rem & 3;
        *(uint4*)(smem + stg_i * STG + 8192 + mat * 7168 + sw64(rr, s * 16)) =
            make_uint4(0, 0, 0, 0);
    }

    auto CPW = [&](int j) {
        const u32 base = sb + (j & 3) * STG;
        const size_t ko = (size_t)j * KC;
        cp16(base +  8192 + woff0, g_Wh + wsrc0 + ko);
        cp16(base + 15360 + woff0, g_Wl + wsrc0 + ko);
        if (w1v) {
            cp16(base +  8192 + woff1, g_Wh + wsrc1 + ko);
            cp16(base + 15360 + woff1, g_Wl + wsrc1 + ko);
        }
    };

    auto STAGE = [&](int j) {
        const size_t g = abase + (size_t)j * KC;
        float v[8], vc[8];
        float4 x0 = *(const float4*)(x + g);
        float4 x1 = *(const float4*)(x + g + 4);
        v[0]=x0.x; v[1]=x0.y; v[2]=x0.z; v[3]=x0.w;
        v[4]=x1.x; v[5]=x1.y; v[6]=x1.z; v[7]=x1.w;
        float4 q0 = *(const float4*)(xr + g);
        float4 q1 = *(const float4*)(xr + g + 4);
        float q[8] = {q0.x,q0.y,q0.z,q0.w,q1.x,q1.y,q1.z,q1.w};
        if (mode == 1) {
            uint2 mm = *(const uint2*)((const unsigned char*)mk + g);
            u32 lo = mm.x, hi = mm.y;
            #pragma unroll
            for (int m = 0; m < 4; m++) {
                vc[m]   = ((lo >> (m*8)) & 0xff) ? q[m]   : v[m];
                vc[m+4] = ((hi >> (m*8)) & 0xff) ? q[m+4] : v[m+4];
            }
        } else if (mode == 0) {
            int4 m0 = *(const int4*)((const int*)mk + g);
            int4 m1 = *(const int4*)((const int*)mk + g + 4);
            int mi[8] = {m0.x,m0.y,m0.z,m0.w,m1.x,m1.y,m1.z,m1.w};
            #pragma unroll
            for (int m = 0; m < 8; m++) vc[m] = mi[m] ? q[m] : v[m];
        } else {
            float4 m0 = *(const float4*)((const float*)mk + g);
            float4 m1 = *(const float4*)((const float*)mk + g + 4);
            float mf_[8] = {m0.x,m0.y,m0.z,m0.w,m1.x,m1.y,m1.z,m1.w};
            #pragma unroll
            for (int m = 0; m < 8; m++) vc[m] = (mf_[m] != 0.f) ? q[m] : v[m];
        }
        uint4 HA0, HA1;
        HA0.x = pk_f16(v[0],v[1]);  HA0.y = pk_f16(v[2],v[3]);
        HA0.z = pk_f16(v[4],v[5]);  HA0.w = pk_f16(v[6],v[7]);
        HA1.x = pk_f16(vc[0],vc[1]); HA1.y = pk_f16(vc[2],vc[3]);
        HA1.z = pk_f16(vc[4],vc[5]); HA1.w = pk_f16(vc[6],vc[7]);
        char* bs = smem + (j & 3) * STG;
        *(uint4*)(bs +        aoff) = HA0;
        *(uint4*)(bs + 4096 + aoff) = HA1;
    };

    const u32 rA0 = lane & 15;
    const u32 c16A = ((lane >> 4) & 1) * 16;
    const u32 xrA0 = ((rA0 >> 1) & 3) << 4;
    const u32 nrow = nc * 32 + ((lane >> 4) & 1) * 8 + (lane & 7);
    const u32 c16B = ((lane >> 3) & 1) * 16;
    const u32 baseB0 = nrow * 64,        xrB0 = ((nrow >> 1) & 3) << 4;
    const u32 baseB1 = (nrow + 16) * 64, xrB1 = (((nrow + 16) >> 1) & 3) << 4;

    auto COMP = [&](int j) {
        const u32 bs = sb + (j & 3) * STG;
        const u32 Ab = bs + pa * 4096;
        const u32 Wh = bs + 8192, Wl = bs + 15360;
        #pragma unroll
        for (int kss = 0; kss < 2; kss++) {
            const u32 kb = kss * 32;
            const u32 ka = (kb + c16A) ^ xrA0;
            u32 aF[4][4];
            #pragma unroll
            for (int mf = 0; mf < 4; mf++)
                ldsm4(aF[mf][0], aF[mf][1], aF[mf][2], aF[mf][3],
                      Ab + rA0 * 64 + mf * 1024 + ka);
            if (nc < 3) {
                u32 bH[4][2], bL[4][2];
                ldsm4(bH[0][0], bH[0][1], bH[1][0], bH[1][1], Wh + baseB0 + ((kb + c16B) ^ xrB0));
                ldsm4(bH[2][0], bH[2][1], bH[3][0], bH[3][1], Wh + baseB1 + ((kb + c16B) ^ xrB1));
                ldsm4(bL[0][0], bL[0][1], bL[1][0], bL[1][1], Wl + baseB0 + ((kb + c16B) ^ xrB0));
                ldsm4(bL[2][0], bL[2][1], bL[3][0], bL[3][1], Wl + baseB1 + ((kb + c16B) ^ xrB1));
                #pragma unroll
                for (int mf = 0; mf < 4; mf++)
                    #pragma unroll
                    for (int nf = 0; nf < 4; nf++) {
                        mma16816(acc[mf][nf], aF[mf], bH[nf]);
                        mma16816(acc[mf][nf], aF[mf], bL[nf]);
                    }
            } else {
                u32 bH[2][2], bL[2][2];
                ldsm4(bH[0][0], bH[0][1], bH[1][0], bH[1][1], Wh + baseB0 + ((kb + c16B) ^ xrB0));
                ldsm4(bL[0][0], bL[0][1], bL[1][0], bL[1][1], Wl + baseB0 + ((kb + c16B) ^ xrB0));
                #pragma unroll
                for (int mf = 0; mf < 4; mf++)
                    #pragma unroll
                    for (int nf = 0; nf < 2; nf++) {
                        mma16816(acc[mf][nf], aF[mf], bH[nf]);
                        mma16816(acc[mf][nf], aF[mf], bL[nf]);
                    }
            }
        }
    };

    CPW(0); CP_COMMIT();
    CPW(1); CP_COMMIT();
    CPW(2); CP_COMMIT();
    STAGE(0);
    STAGE(1);
    CP_WAIT1();
    __syncthreads();

    int i = 0;
    for (; i + 1 < n; i += 2) {
        COMP(i);
        if (i + 2 < n) STAGE(i + 2);
        COMP(i + 1);
        if (i + 3 < n) STAGE(i + 3);
        if (i + 3 < n) CPW(i + 3);
        CP_COMMIT();
        if (i + 4 < n) CPW(i + 4);
        CP_COMMIT();
        CP_WAIT1();
        __syncthreads();
    }
    if (i < n) COMP(i);

    float* Pp = &g_Part[ks][pa][0][0];
    const int gq = lane >> 2, tt = lane & 3;
    #pragma unroll
    for (int mf = 0; mf < 4; mf++)
        #pragma unroll
        for (int nf = 0; nf < 4; nf++) {
            const int col = nc * 32 + nf * 8 + 2 * tt;
            if (col < EMB) {
                const int ra = r0g + mf * 16 + gq;
                *(float2*)&Pp[(size_t)ra * 104 + col] =
                    make_float2(acc[mf][nf][0], acc[mf][nf][1]);
                *(float2*)&Pp[(size_t)(ra + 8) * 104 + col] =
                    make_float2(acc[mf][nf][2], acc[mf][nf][3]);
            }
        }
}

// ---------------- persistent tail: merge + 3 layers, grid-wide barriers ----
// grid 256, occ 2 -> all CTAs co-resident (148*2 = 296 slots >= 256).
__device__ __forceinline__ void gbar_stats(int ph, int stage,
    const float* gamma, const float* beta, int t)
{
    __shared__ int s_old;
    __threadfence();
    if (t == 0) s_old = atomicAdd(&g_cnt[ph], 1);
    __syncthreads();
    if (s_old == 255) {
        // last arriver: all partials visible; compute BN scale/shift
        if (t < 200) {
            const int pp = t / 100, c = t % 100;
            float s = 0.f, s2 = 0.f;
            #pragma unroll 4
            for (int it = 0; it < 128; it++) {
                s  += g_P[stage][pp][it][0][c];
                s2 += g_P[stage][pp][it][1][c];
            }
            float mu  = s * (1.f / BR);
            float var = s2 * (1.f / BR) - mu * mu;
            float sv  = gamma[c] * rsqrtf(var + EPSB);
            g_scb[stage][pp][0][c] = sv;
            g_scb[stage][pp][1][c] = beta[c] - mu * sv;
        }
        __syncthreads();
        __threadfence();
        if (t == 0) atomicExch(&g_flag[ph], 1);
    } else {
        if (t == 0) {
            while (atomicAdd(&g_flag[ph], 0) == 0) __nanosleep(64);
        }
        __syncthreads();
    }
}

__device__ void layer_body(const float* __restrict__ Hin, float* __restrict__ Hout,
                           const float* __restrict__ W, const float* __restrict__ bias,
                           int stage, bool rin, bool rout, bool partials,
                           int p, int tile, float* sm, int t)
{
    float* Hs  = sm;            // 100*33
    float* Ws  = sm + 3300;     // 100*132
    float* red = sm + 16500;    // 2048
    float* sc  = sm + 18548;
    float* sh  = sm + 18676;
    const int r0 = tile * 32;
    const int ty = t >> 4, tx = t & 15;

    if (t < EMB) {
        sc[t] = g_scb[stage][p][0][t];
        sh[t] = g_scb[stage][p][1][t];
    }
    __syncthreads();

    const float* Hp = Hin + (size_t)p * BR * EMB;
    for (int i = t; i < 32 * EMB; i += 256) {
        int row = i / EMB, k = i % EMB;
        float v = Hp[(size_t)(r0 + row) * EMB + k] * sc[k] + sh[k];
        if (rin) v = fmaxf(v, 0.f);
        Hs[k * 33 + row] = v;
    }
    for (int i = t; i < EMB * EMB; i += 256) {
        int nn = i / EMB, k = i % EMB;
        Ws[k * 132 + nn] = W[i];
    }
    for (int i = t; i < EMB * 28; i += 256) {
        int k = i / 28, nn = 100 + i % 28;
        Ws[k * 132 + nn] = 0.f;
    }
    __syncthreads();

    u64 acc[2][4];
    #pragma unroll
    for (int r = 0; r < 2; r++)
        #pragma unroll
        for (int c = 0; c < 4; c++) acc[r][c] = 0ull;

    #pragma unroll 4
    for (int k = 0; k < EMB; k++) {
        const float* ak = Hs + k * 33 + ty * 2;
        float a0 = ak[0], a1 = ak[1];
        const u64* wp = (const u64*)(Ws + k * 132 + tx * 8);
        u64 b0 = wp[0], b1 = wp[1], b2 = wp[2], b3 = wp[3];
        u64 A0 = pk2(a0, a0), A1 = pk2(a1, a1);
        acc[0][0]=fma2(A0,b0,acc[0][0]); acc[0][1]=fma2(A0,b1,acc[0][1]);
        acc[0][2]=fma2(A0,b2,acc[0][2]); acc[0][3]=fma2(A0,b3,acc[0][3]);
        acc[1][0]=fma2(A1,b0,acc[1][0]); acc[1][1]=fma2(A1,b1,acc[1][1]);
        acc[1][2]=fma2(A1,b2,acc[1][2]); acc[1][3]=fma2(A1,b3,acc[1][3]);
    }

    float vo[2][8];
    #pragma unroll
    for (int r = 0; r < 2; r++) {
        int row = r0 + ty * 2 + r;
        #pragma unroll
        for (int cp = 0; cp < 4; cp++) {
            float2 f = upk2(acc[r][cp]);
            #pragma unroll
            for (int hh = 0; hh < 2; hh++) {
                int col = tx * 8 + cp * 2 + hh;
                float v = (hh ? f.y : f.x) + (col < EMB ? bias[col] : 0.f);
                if (rout) v = fmaxf(v, 0.f);
                vo[r][cp * 2 + hh] = v;
                if (col < EMB)
                    Hout[((size_t)p * BR + row) * EMB + col] = v;
            }
        }
    }
    if (partials) {
        __syncthreads();
        #pragma unroll
        for (int c = 0; c < 8; c++)
            red[ty * 128 + tx * 8 + c] = vo[0][c] + vo[1][c];
        __syncthreads();
        if (t < 128) {
            float s = 0.f;
            #pragma unroll
            for (int g = 0; g < 16; g++) s += red[g * 128 + t];
            if (t < EMB) g_P[stage + 1][p][tile][0][t] = s;
        }
        __syncthreads();
        #pragma unroll
        for (int c = 0; c < 8; c++)
            red[ty * 128 + tx * 8 + c] = vo[0][c]*vo[0][c] + vo[1][c]*vo[1][c];
        __syncthreads();
        if (t < 128) {
            float s = 0.f;
            #pragma unroll
            for (int g = 0; g < 16; g++) s += red[g * 128 + t];
            if (t < EMB) g_P[stage + 1][p][tile][1][t] = s;
        }
    }
    __syncthreads();
}

__global__ __launch_bounds__(256, 2)
void k_tail(const float* __restrict__ b1,
            const float* __restrict__ g1,  const float* __restrict__ be1,
            const float* __restrict__ w2,  const float* __restrict__ b2,
            const float* __restrict__ g2,  const float* __restrict__ be2,
            const float* __restrict__ hw1, const float* __restrict__ hb1,
            const float* __restrict__ hg1, const float* __restrict__ hbe1,
            const float* __restrict__ hw2, const float* __restrict__ hb2,
            float* __restrict__ out)
{
    extern __shared__ float sm[];
    const int t = threadIdx.x;
    const int p = blockIdx.x >> 7, tile = blockIdx.x & 127;
    const int r0 = tile * 32;

    // ---- phase 0: merge K-splits -> H1 + stage-0 partials ----
    {
        float* Ds = sm;   // [32][104]
        const int r = t >> 3, cg = t & 7;
        const size_t row = (size_t)r0 + r;
        #pragma unroll
        for (int j = 0; j < 13; j++) {
            const int c = cg * 13 + j;
            if (c < EMB) {
                float v = (g_Part[0][p][row][c] + g_Part[1][p][row][c]
                         + g_Part[2][p][row][c] + g_Part[3][p][row][c]) * (1.0f / WSC)
                         + b1[c];
                v = fmaxf(v, 0.f);
                g_H1[((size_t)p * BR + row) * EMB + c] = v;
                Ds[r * 104 + c] = v;
            }
        }
        __syncthreads();
        if (t < EMB) {
            float s = 0.f, s2 = 0.f;
            #pragma unroll 8
            for (int rr = 0; rr < 32; rr++) { float u = Ds[rr * 104 + t]; s += u; s2 += u * u; }
            g_P[0][p][tile][0][t] = s;
            g_P[0][p][tile][1][t] = s2;
        }
        __syncthreads();
    }
    gbar_stats(0, 0, g1, be1, t);

    // ---- phase 1: enc layer 2 (BN0 on input, relu out) ----
    layer_body(g_H1, g_H2, w2, b2, 0, false, true, true, p, tile, sm, t);
    gbar_stats(1, 1, g2, be2, t);

    // ---- phase 2: head layer 1 (BN1 on input) ----
    layer_body(g_H2, g_H3, hw1, hb1, 1, false, false, true, p, tile, sm, t);
    gbar_stats(2, 2, hg1, hbe1, t);

    // ---- phase 3: head layer 2 (relu(BN2) on input) -> out ----
    layer_body(g_H3, out, hw2, hb2, 2, true, false, false, p, tile, sm, t);
}

// ---------------- launch ----------------
extern "C" void kernel_launch(void* const* d_in, const int* in_sizes, int n_in,
                              void* d_out, int out_size)
{
    const float* x   = (const float*)d_in[0];
    const void*  mk  = d_in[1];
    const float* xr  = (const float*)d_in[2];
    const float* w1  = (const float*)d_in[3];
    const float* b1  = (const float*)d_in[4];
    const float* g1  = (const float*)d_in[5];
    const float* be1 = (const float*)d_in[6];
    const float* w2  = (const float*)d_in[7];
    const float* b2  = (const float*)d_in[8];
    const float* g2  = (const float*)d_in[9];
    const float* be2 = (const float*)d_in[10];
    const float* hw1 = (const float*)d_in[11];
    const float* hb1 = (const float*)d_in[12];
    const float* hg1 = (const float*)d_in[13];
    const float* hbe1= (const float*)d_in[14];
    const float* hw2 = (const float*)d_in[15];
    const float* hb2 = (const float*)d_in[16];
    float* out = (float*)d_out;

    cudaFuncSetAttribute(k_big,  cudaFuncAttributeMaxDynamicSharedMemorySize, NSTG * STG);
    cudaFuncSetAttribute(k_tail, cudaFuncAttributeMaxDynamicSharedMemorySize, 76816);

    const int H = WROWS * MF / 2 / 2;
    k_detect<<<1, 256>>>((const unsigned char*)mk);          // 1
    k_wcvt<<<(H + 255) / 256, 256>>>(w1, 0);                 // 2
    k_wcvt<<<(H + 255) / 256, 256>>>(w1, H);                 // 3
    k_big<<<256, 256, NSTG * STG>>>(x, mk, xr);              // 4 <- profiled
    k_tail<<<256, 256, 76816>>>(b1, g1, be1, w2, b2, g2, be2,
                                hw1, hb1, hg1, hbe1, hw2, hb2, out);
}

// round 16
// speedup vs baseline: 1.2114x; 1.0786x over previous
#include <cuda_runtime.h>
#include <cuda_fp16.h>
#include <cstdint>
#include <cstddef>

#define BR    4096
#define MF    20000
#define EMB   100
#define WROWS 104
#define KC    32
#define KSPL  4
#define EPSB  1e-5f
#define STG   22528         // A(p0) 4K | A(p1) 4K | Wh 7K | Wl 7K
#define NSTG  4
#define WSC   64.0f

typedef unsigned long long u64;
typedef unsigned int u32;

// ---------------- device scratch ----------------
__device__ int   g_mode;
__device__ unsigned short g_Wh[WROWS * MF];
__device__ unsigned short g_Wl[WROWS * MF];
__device__ float g_Part[KSPL][2][BR][104];
__device__ float g_P[3][2][128][2][EMB];       // stage, pass, tile32, {sum,sumsq}, col
__device__ float g_scb[3][2][2][EMB];          // stage, pass, {scale,shift}, col
__device__ int   g_cnt[3];
__device__ int   g_flag[3];

// ---------------- helpers ----------------
__device__ __forceinline__ u32 smem_u32(const void* p) {
    u32 a; asm("{ .reg .u64 t; cvta.to.shared.u64 t, %1; cvt.u32.u64 %0, t; }" : "=r"(a) : "l"(p));
    return a;
}
__device__ __forceinline__ void ldsm4(u32& r0, u32& r1, u32& r2, u32& r3, u32 addr) {
    asm volatile("ldmatrix.sync.aligned.m8n8.x4.shared.b16 {%0,%1,%2,%3}, [%4];"
        : "=r"(r0), "=r"(r1), "=r"(r2), "=r"(r3) : "r"(addr));
}
__device__ __forceinline__ void mma16816(float* d, const u32* a, const u32* b) {
    asm volatile("mma.sync.aligned.m16n8k16.row.col.f32.f16.f16.f32 "
        "{%0,%1,%2,%3}, {%4,%5,%6,%7}, {%8,%9}, {%0,%1,%2,%3};"
        : "+f"(d[0]), "+f"(d[1]), "+f"(d[2]), "+f"(d[3])
        : "r"(a[0]), "r"(a[1]), "r"(a[2]), "r"(a[3]), "r"(b[0]), "r"(b[1]));
}
__device__ __forceinline__ void cp16(u32 dst, const void* src) {
    asm volatile("cp.async.cg.shared.global [%0], [%1], 16;"
        :: "r"(dst), "l"(src) : "memory");
}
#define CP_COMMIT() asm volatile("cp.async.commit_group;" ::: "memory")
#define CP_WAIT1()  asm volatile("cp.async.wait_group 1;" ::: "memory")

__device__ __forceinline__ u32 sw64(u32 row, u32 colb) {
    return row * 64 + (colb ^ (((row >> 1) & 3) << 4));
}
__device__ __forceinline__ u32 pk_f16(float lo, float hi) {
    u32 r; asm("cvt.rn.f16x2.f32 %0, %1, %2;" : "=r"(r) : "f"(hi), "f"(lo));
    return r;
}
__device__ __forceinline__ u64 pk2(float lo, float hi) {
    u64 d; asm("mov.b64 %0, {%1, %2};" : "=l"(d) : "f"(lo), "f"(hi)); return d;
}
__device__ __forceinline__ u64 fma2(u64 a, u64 b, u64 c) {
    u64 d; asm("fma.rn.f32x2 %0, %1, %2, %3;" : "=l"(d) : "l"(a), "l"(b), "l"(c)); return d;
}
__device__ __forceinline__ float2 upk2(u64 v) {
    float2 r; asm("mov.b64 {%0, %1}, %2;" : "=f"(r.x), "=f"(r.y) : "l"(v)); return r;
}

// ---------------- mask dtype classifier + counter reset ----------------
__global__ void k_detect(const unsigned char* __restrict__ m) {
    __shared__ int s_nz, s_gt;
    if (threadIdx.x < 3) { g_cnt[threadIdx.x] = 0; g_flag[threadIdx.x] = 0; }
    if (threadIdx.x == 0) { s_nz = 0; s_gt = 0; }
    __syncthreads();
    int nz = 0, gt = 0;
    for (int i = threadIdx.x; i < 65536; i += blockDim.x) {
        unsigned char v = m[i];
        nz += (v != 0); gt += (v > 1);
    }
    atomicAdd(&s_nz, nz); atomicAdd(&s_gt, gt);
    __syncthreads();
    if (threadIdx.x == 0)
        g_mode = (s_gt > 64) ? 2 : (s_nz > 24576) ? 1 : 0;
}

// ---------------- W split precompute ----------------
__global__ void k_wcvt(const float* __restrict__ w, int base) {
    int i = base + blockIdx.x * blockDim.x + threadIdx.x;
    if (i >= WROWS * MF / 2) return;
    int row = i / (MF / 2), within = i % (MF / 2);
    if (row < EMB) {
        float2 v = *(const float2*)(w + (size_t)row * MF + 2 * within);
        float sx = WSC * v.x, sy = WSC * v.y;
        float hx = __half2float(__float2half_rn(sx));
        float hy = __half2float(__float2half_rn(sy));
        ((u32*)g_Wh)[i] = pk_f16(hx, hy);
        ((u32*)g_Wl)[i] = pk_f16(sx - hx, sy - hy);
    } else {
        ((u32*)g_Wh)[i] = 0u;
        ((u32*)g_Wl)[i] = 0u;
    }
}

// ---------------- Layer 1: 2-term fp16 mma.sync (R13 verbatim) -------------
__global__ __launch_bounds__(256, 2)
void k_big(const float* __restrict__ x, const void* __restrict__ mk,
           const float* __restrict__ xr)
{
    extern __shared__ char smem[];
    const u32 sb = smem_u32(smem);
    const int t = threadIdx.x;
    const int w = t >> 5, lane = t & 31;
    const int tile = blockIdx.x >> 2, ks = blockIdx.x & 3;
    const int r0g = tile * 64;
    const int ci0 = ks ? (157 + 156 * (ks - 1)) : 0;
    const int n   = ks ? 156 : 157;
    const size_t k0g = (size_t)ci0 * KC;
    const int pa = w >> 2, nc = w & 3;
    const int mode = g_mode;

    const int arow = t >> 2, seg = t & 3;
    const size_t abase = (size_t)(r0g + arow) * MF + k0g + (size_t)seg * 8;
    const u32 aoff = sw64(arow, seg * 16);

    const int gi1 = t + 256;
    const bool w1v = (gi1 < 416);
    const int wr0 = t >> 2, wsg0 = t & 3;
    const int wr1 = gi1 >> 2, wsg1 = gi1 & 3;
    const u32 woff0 = sw64(wr0, wsg0 * 16);
    const u32 woff1 = sw64(wr1, wsg1 * 16);
    const size_t wsrc0 = (size_t)wr0 * MF + k0g + (size_t)wsg0 * 8;
    const size_t wsrc1 = (size_t)wr1 * MF + k0g + (size_t)wsg1 * 8;

    float acc[4][4][4];
    #pragma unroll
    for (int mf = 0; mf < 4; mf++)
        #pragma unroll
        for (int nf = 0; nf < 4; nf++)
            #pragma unroll
            for (int e = 0; e < 4; e++) acc[mf][nf][e] = 0.f;

    {
        const int stg_i = t >> 6, rem = t & 63;
        const int mat = rem >> 5, rr = 104 + ((rem & 31) >> 2), s = rem & 3;
        *(uint4*)(smem + stg_i * STG + 8192 + mat * 7168 + sw64(rr, s * 16)) =
            make_uint4(0, 0, 0, 0);
    }

    auto CPW = [&](int j) {
        const u32 base = sb + (j & 3) * STG;
        const size_t ko = (size_t)j * KC;
        cp16(base +  8192 + woff0, g_Wh + wsrc0 + ko);
        cp16(base + 15360 + woff0, g_Wl + wsrc0 + ko);
        if (w1v) {
            cp16(base +  8192 + woff1, g_Wh + wsrc1 + ko);
            cp16(base + 15360 + woff1, g_Wl + wsrc1 + ko);
        }
    };

    auto STAGE = [&](int j) {
        const size_t g = abase + (size_t)j * KC;
        float v[8], vc[8];
        float4 x0 = *(const float4*)(x + g);
        float4 x1 = *(const float4*)(x + g + 4);
        v[0]=x0.x; v[1]=x0.y; v[2]=x0.z; v[3]=x0.w;
        v[4]=x1.x; v[5]=x1.y; v[6]=x1.z; v[7]=x1.w;
        float4 q0 = *(const float4*)(xr + g);
        float4 q1 = *(const float4*)(xr + g + 4);
        float q[8] = {q0.x,q0.y,q0.z,q0.w,q1.x,q1.y,q1.z,q1.w};
        if (mode == 1) {
            uint2 mm = *(const uint2*)((const unsigned char*)mk + g);
            u32 lo = mm.x, hi = mm.y;
            #pragma unroll
            for (int m = 0; m < 4; m++) {
                vc[m]   = ((lo >> (m*8)) & 0xff) ? q[m]   : v[m];
                vc[m+4] = ((hi >> (m*8)) & 0xff) ? q[m+4] : v[m+4];
            }
        } else if (mode == 0) {
            int4 m0 = *(const int4*)((const int*)mk + g);
            int4 m1 = *(const int4*)((const int*)mk + g + 4);
            int mi[8] = {m0.x,m0.y,m0.z,m0.w,m1.x,m1.y,m1.z,m1.w};
            #pragma unroll
            for (int m = 0; m < 8; m++) vc[m] = mi[m] ? q[m] : v[m];
        } else {
            float4 m0 = *(const float4*)((const float*)mk + g);
            float4 m1 = *(const float4*)((const float*)mk + g + 4);
            float mf_[8] = {m0.x,m0.y,m0.z,m0.w,m1.x,m1.y,m1.z,m1.w};
            #pragma unroll
            for (int m = 0; m < 8; m++) vc[m] = (mf_[m] != 0.f) ? q[m] : v[m];
        }
        uint4 HA0, HA1;
        HA0.x = pk_f16(v[0],v[1]);  HA0.y = pk_f16(v[2],v[3]);
        HA0.z = pk_f16(v[4],v[5]);  HA0.w = pk_f16(v[6],v[7]);
        HA1.x = pk_f16(vc[0],vc[1]); HA1.y = pk_f16(vc[2],vc[3]);
        HA1.z = pk_f16(vc[4],vc[5]); HA1.w = pk_f16(vc[6],vc[7]);
        char* bs = smem + (j & 3) * STG;
        *(uint4*)(bs +        aoff) = HA0;
        *(uint4*)(bs + 4096 + aoff) = HA1;
    };

    const u32 rA0 = lane & 15;
    const u32 c16A = ((lane >> 4) & 1) * 16;
    const u32 xrA0 = ((rA0 >> 1) & 3) << 4;
    const u32 nrow = nc * 32 + ((lane >> 4) & 1) * 8 + (lane & 7);
    const u32 c16B = ((lane >> 3) & 1) * 16;
    const u32 baseB0 = nrow * 64,        xrB0 = ((nrow >> 1) & 3) << 4;
    const u32 baseB1 = (nrow + 16) * 64, xrB1 = (((nrow + 16) >> 1) & 3) << 4;

    auto COMP = [&](int j) {
        const u32 bs = sb + (j & 3) * STG;
        const u32 Ab = bs + pa * 4096;
        const u32 Wh = bs + 8192, Wl = bs + 15360;
        #pragma unroll
        for (int kss = 0; kss < 2; kss++) {
            const u32 kb = kss * 32;
            const u32 ka = (kb + c16A) ^ xrA0;
            u32 aF[4][4];
            #pragma unroll
            for (int mf = 0; mf < 4; mf++)
                ldsm4(aF[mf][0], aF[mf][1], aF[mf][2], aF[mf][3],
                      Ab + rA0 * 64 + mf * 1024 + ka);
            if (nc < 3) {
                u32 bH[4][2], bL[4][2];
                ldsm4(bH[0][0], bH[0][1], bH[1][0], bH[1][1], Wh + baseB0 + ((kb + c16B) ^ xrB0));
                ldsm4(bH[2][0], bH[2][1], bH[3][0], bH[3][1], Wh + baseB1 + ((kb + c16B) ^ xrB1));
                ldsm4(bL[0][0], bL[0][1], bL[1][0], bL[1][1], Wl + baseB0 + ((kb + c16B) ^ xrB0));
                ldsm4(bL[2][0], bL[2][1], bL[3][0], bL[3][1], Wl + baseB1 + ((kb + c16B) ^ xrB1));
                #pragma unroll
                for (int mf = 0; mf < 4; mf++)
                    #pragma unroll
                    for (int nf = 0; nf < 4; nf++) {
                        mma16816(acc[mf][nf], aF[mf], bH[nf]);
                        mma16816(acc[mf][nf], aF[mf], bL[nf]);
                    }
            } else {
                u32 bH[2][2], bL[2][2];
                ldsm4(bH[0][0], bH[0][1], bH[1][0], bH[1][1], Wh + baseB0 + ((kb + c16B) ^ xrB0));
                ldsm4(bL[0][0], bL[0][1], bL[1][0], bL[1][1], Wl + baseB0 + ((kb + c16B) ^ xrB0));
                #pragma unroll
                for (int mf = 0; mf < 4; mf++)
                    #pragma unroll
                    for (int nf = 0; nf < 2; nf++) {
                        mma16816(acc[mf][nf], aF[mf], bH[nf]);
                        mma16816(acc[mf][nf], aF[mf], bL[nf]);
                    }
            }
        }
    };

    CPW(0); CP_COMMIT();
    CPW(1); CP_COMMIT();
    CPW(2); CP_COMMIT();
    STAGE(0);
    STAGE(1);
    CP_WAIT1();
    __syncthreads();

    int i = 0;
    for (; i + 1 < n; i += 2) {
        COMP(i);
        if (i + 2 < n) STAGE(i + 2);
        COMP(i + 1);
        if (i + 3 < n) STAGE(i + 3);
        if (i + 3 < n) CPW(i + 3);
        CP_COMMIT();
        if (i + 4 < n) CPW(i + 4);
        CP_COMMIT();
        CP_WAIT1();
        __syncthreads();
    }
    if (i < n) COMP(i);

    float* Pp = &g_Part[ks][pa][0][0];
    const int gq = lane >> 2, tt = lane & 3;
    #pragma unroll
    for (int mf = 0; mf < 4; mf++)
        #pragma unroll
        for (int nf = 0; nf < 4; nf++) {
            const int col = nc * 32 + nf * 8 + 2 * tt;
            if (col < EMB) {
                const int ra = r0g + mf * 16 + gq;
                *(float2*)&Pp[(size_t)ra * 104 + col] =
                    make_float2(acc[mf][nf][0], acc[mf][nf][1]);
                *(float2*)&Pp[(size_t)(ra + 8) * 104 + col] =
                    make_float2(acc[mf][nf][2], acc[mf][nf][3]);
            }
        }
}

// ---------------- persistent tail v2: H resident in SMEM -------------------
// grid 256 (= 2 passes x 128 tiles of 32 rows), occ 2 -> all co-resident.
// smem (floats): Hs[3300] | Hb[3300] | Ws[13200] | red[2048] | sc[128] | sh[128]
#define T_HS  0
#define T_HB  3300
#define T_WS  6600
#define T_RED 19800
#define T_SC  21848
#define T_SH  21976
#define T_TOT 22104

__device__ __forceinline__ void tail_bar(int ph, int stage,
    const float* gamma, const float* beta, int t)
{
    __shared__ int s_old;
    __threadfence();
    if (t == 0) s_old = atomicAdd(&g_cnt[ph], 1);
    __syncthreads();
    if (s_old == 255) {
        if (t < 200) {
            const int pp = t / 100, c = t % 100;
            float s = 0.f, s2 = 0.f;
            #pragma unroll 8
            for (int it = 0; it < 128; it++) {
                s  += g_P[stage][pp][it][0][c];
                s2 += g_P[stage][pp][it][1][c];
            }
            float mu  = s * (1.f / BR);
            float var = s2 * (1.f / BR) - mu * mu;
            float sv  = gamma[c] * rsqrtf(var + EPSB);
            g_scb[stage][pp][0][c] = sv;
            g_scb[stage][pp][1][c] = beta[c] - mu * sv;
        }
        __syncthreads();
        __threadfence();
        if (t == 0) atomicExch(&g_flag[ph], 1);
    } else {
        if (t == 0) {
            while (atomicAdd(&g_flag[ph], 0) == 0) __nanosleep(64);
        }
        __syncthreads();
    }
}

// prefetch 100x100 W into 10 uint4 regs
__device__ __forceinline__ void w_fetch(const float* __restrict__ W, uint4* wr, int t) {
    #pragma unroll
    for (int j = 0; j < 10; j++) {
        int f = t + 256 * j;
        wr[j] = (f < 2500) ? *(const uint4*)(W + 4 * f) : make_uint4(0, 0, 0, 0);
    }
}
// transpose regs -> Ws[k*132+nn]
__device__ __forceinline__ void w_unpack(float* Ws, const uint4* wr, int t) {
    #pragma unroll
    for (int j = 0; j < 10; j++) {
        int f = t + 256 * j;
        if (f < 2500) {
            int nn = f / 25, kq = (f % 25) * 4;
            Ws[(kq    ) * 132 + nn] = __uint_as_float(wr[j].x);
            Ws[(kq + 1) * 132 + nn] = __uint_as_float(wr[j].y);
            Ws[(kq + 2) * 132 + nn] = __uint_as_float(wr[j].z);
            Ws[(kq + 3) * 132 + nn] = __uint_as_float(wr[j].w);
        }
    }
}

// GEMM: Hb (A, [k*33+row]) x Ws -> vo; writeback to Hs or out; partials to g_P[stage+1]
__device__ void tail_gemm(float* sm, const float* __restrict__ bias,
                          bool rout, int outstage, int p, int tile,
                          float* __restrict__ out, int t)
{
    float* Hb = sm + T_HB;
    float* Ws = sm + T_WS;
    float* red = sm + T_RED;
    const int ty = t >> 4, tx = t & 15;

    u64 acc[2][4];
    #pragma unroll
    for (int r = 0; r < 2; r++)
        #pragma unroll
        for (int c = 0; c < 4; c++) acc[r][c] = 0ull;

    #pragma unroll 4
    for (int k = 0; k < EMB; k++) {
        const float* ak = Hb + k * 33 + ty * 2;
        float a0 = ak[0], a1 = ak[1];
        const u64* wp = (const u64*)(Ws + k * 132 + tx * 8);
        u64 b0 = wp[0], b1 = wp[1], b2 = wp[2], b3 = wp[3];
        u64 A0 = pk2(a0, a0), A1 = pk2(a1, a1);
        acc[0][0]=fma2(A0,b0,acc[0][0]); acc[0][1]=fma2(A0,b1,acc[0][1]);
        acc[0][2]=fma2(A0,b2,acc[0][2]); acc[0][3]=fma2(A0,b3,acc[0][3]);
        acc[1][0]=fma2(A1,b0,acc[1][0]); acc[1][1]=fma2(A1,b1,acc[1][1]);
        acc[1][2]=fma2(A1,b2,acc[1][2]); acc[1][3]=fma2(A1,b3,acc[1][3]);
    }

    float* Hs = sm + T_HS;
    float vo[2][8];
    #pragma unroll
    for (int r = 0; r < 2; r++) {
        const int row_l = ty * 2 + r;
        #pragma unroll
        for (int cp = 0; cp < 4; cp++) {
            float2 f = upk2(acc[r][cp]);
            #pragma unroll
            for (int hh = 0; hh < 2; hh++) {
                int col = tx * 8 + cp * 2 + hh;
                float v = (hh ? f.y : f.x) + (col < EMB ? bias[col] : 0.f);
                if (rout) v = fmaxf(v, 0.f);
                vo[r][cp * 2 + hh] = v;
                if (col < EMB) {
                    if (out) out[((size_t)p * BR + tile * 32 + row_l) * EMB + col] = v;
                    else     Hs[col * 33 + row_l] = v;
                }
            }
        }
    }
    if (outstage >= 0) {
        __syncthreads();
        #pragma unroll
        for (int c = 0; c < 8; c++)
            red[ty * 128 + tx * 8 + c] = vo[0][c] + vo[1][c];
        __syncthreads();
        if (t < 128) {
            float s = 0.f;
            #pragma unroll
            for (int g = 0; g < 16; g++) s += red[g * 128 + t];
            if (t < EMB) g_P[outstage][p][tile][0][t] = s;
        }
        __syncthreads();
        #pragma unroll
        for (int c = 0; c < 8; c++)
            red[ty * 128 + tx * 8 + c] = vo[0][c]*vo[0][c] + vo[1][c]*vo[1][c];
        __syncthreads();
        if (t < 128) {
            float s = 0.f;
            #pragma unroll
            for (int g = 0; g < 16; g++) s += red[g * 128 + t];
            if (t < EMB) g_P[outstage][p][tile][1][t] = s;
        }
    }
    __syncthreads();
}

// Hb = BN(Hs) (+optional relu)
__device__ __forceinline__ void bn_apply(float* sm, bool rin, int t) {
    float* Hs = sm + T_HS;
    float* Hb = sm + T_HB;
    float* sc = sm + T_SC;
    float* sh = sm + T_SH;
    #pragma unroll
    for (int j = 0; j < 13; j++) {
        int i = t + 256 * j;
        if (i < 3300) {
            int k = i / 33;
            float v = Hs[i] * sc[k] + sh[k];
            if (rin) v = fmaxf(v, 0.f);
            Hb[i] = v;
        }
    }
    __syncthreads();
}
__device__ __forceinline__ void scb_load(float* sm, int stage, int p, int t) {
    if (t < EMB) {
        sm[T_SC + t] = g_scb[stage][p][0][t];
        sm[T_SH + t] = g_scb[stage][p][1][t];
    }
}

__global__ __launch_bounds__(256, 2)
void k_tail2(const float* __restrict__ b1,
             const float* __restrict__ g1,  const float* __restrict__ be1,
             const float* __restrict__ w2,  const float* __restrict__ b2,
             const float* __restrict__ g2,  const float* __restrict__ be2,
             const float* __restrict__ hw1, const float* __restrict__ hb1,
             const float* __restrict__ hg1, const float* __restrict__ hbe1,
             const float* __restrict__ hw2, const float* __restrict__ hb2,
             float* __restrict__ out)
{
    extern __shared__ float sm[];
    const int t = threadIdx.x;
    const int p = blockIdx.x >> 7, tile = blockIdx.x & 127;
    const int r0 = tile * 32;
    float* Hs = sm + T_HS;
    float* Ws = sm + T_WS;
    uint4 wreg[10];

    // zero Ws pad cols (100..127), stays zero across all phases
    for (int i = t; i < 2800; i += 256) {
        int k = i / 28, nn = 100 + i % 28;
        Ws[k * 132 + nn] = 0.f;
    }

    // prefetch W for phase 1 early
    w_fetch(w2, wreg, t);

    // ---- phase 0: merge K-splits -> Hs + stage-0 partials ----
    {
        #pragma unroll
        for (int j = 0; j < 4; j++) {
            int f = t + 256 * j;
            if (f < 832) {
                int row = f / 26, cq = (f % 26) * 4;
                const float* P0 = &g_Part[0][p][r0 + row][cq];
                const float* P1 = &g_Part[1][p][r0 + row][cq];
                const float* P2 = &g_Part[2][p][r0 + row][cq];
                const float* P3 = &g_Part[3][p][r0 + row][cq];
                float4 a = *(const float4*)P0, b = *(const float4*)P1;
                float4 c = *(const float4*)P2, d = *(const float4*)P3;
                float v[4] = { a.x+b.x+c.x+d.x, a.y+b.y+c.y+d.y,
                               a.z+b.z+c.z+d.z, a.w+b.w+c.w+d.w };
                #pragma unroll
                for (int e = 0; e < 4; e++) {
                    int cc = cq + e;
                    if (cc < EMB) {
                        float u = fmaxf(v[e] * (1.0f / WSC) + b1[cc], 0.f);
                        Hs[cc * 33 + row] = u;
                    }
                }
            }
        }
        __syncthreads();
        if (t < EMB) {
            float s = 0.f, s2 = 0.f;
            #pragma unroll 8
            for (int r = 0; r < 32; r++) { float u = Hs[t * 33 + r]; s += u; s2 += u * u; }
            g_P[0][p][tile][0][t] = s;
            g_P[0][p][tile][1][t] = s2;
        }
        __syncthreads();
    }
    tail_bar(0, 0, g1, be1, t);

    // ---- phase 1: enc layer 2 (BN0 in, relu out) ----
    w_unpack(Ws, wreg, t);
    scb_load(sm, 0, p, t);
    __syncthreads();
    bn_apply(sm, false, t);
    tail_gemm(sm, b2, true, 1, p, tile, nullptr, t);
    w_fetch(hw1, wreg, t);
    tail_bar(1, 1, g2, be2, t);

    // ---- phase 2: head layer 1 (BN1 in, no relu) ----
    w_unpack(Ws, wreg, t);
    scb_load(sm, 1, p, t);
    __syncthreads();
    bn_apply(sm, false, t);
    tail_gemm(sm, hb1, false, 2, p, tile, nullptr, t);
    w_fetch(hw2, wreg, t);
    tail_bar(2, 2, hg1, hbe1, t);

    // ---- phase 3: head layer 2 (relu(BN2) in) -> out ----
    w_unpack(Ws, wreg, t);
    scb_load(sm, 2, p, t);
    __syncthreads();
    bn_apply(sm, true, t);
    tail_gemm(sm, hb2, false, -1, p, tile, out, t);
}

// ---------------- launch ----------------
extern "C" void kernel_launch(void* const* d_in, const int* in_sizes, int n_in,
                              void* d_out, int out_size)
{
    const float* x   = (const float*)d_in[0];
    const void*  mk  = d_in[1];
    const float* xr  = (const float*)d_in[2];
    const float* w1  = (const float*)d_in[3];
    const float* b1  = (const float*)d_in[4];
    const float* g1  = (const float*)d_in[5];
    const float* be1 = (const float*)d_in[6];
    const float* w2  = (const float*)d_in[7];
    const float* b2  = (const float*)d_in[8];
    const float* g2  = (const float*)d_in[9];
    const float* be2 = (const float*)d_in[10];
    const float* hw1 = (const float*)d_in[11];
    const float* hb1 = (const float*)d_in[12];
    const float* hg1 = (const float*)d_in[13];
    const float* hbe1= (const float*)d_in[14];
    const float* hw2 = (const float*)d_in[15];
    const float* hb2 = (const float*)d_in[16];
    float* out = (float*)d_out;

    cudaFuncSetAttribute(k_big,   cudaFuncAttributeMaxDynamicSharedMemorySize, NSTG * STG);
    cudaFuncSetAttribute(k_tail2, cudaFuncAttributeMaxDynamicSharedMemorySize, T_TOT * 4);

    const int H = WROWS * MF / 2 / 2;
    k_detect<<<1, 256>>>((const unsigned char*)mk);          // 1
    k_wcvt<<<(H + 255) / 256, 256>>>(w1, 0);                 // 2
    k_wcvt<<<(H + 255) / 256, 256>>>(w1, H);                 // 3
    k_big<<<256, 256, NSTG * STG>>>(x, mk, xr);              // 4 <- profiled
    k_tail2<<<256, 256, T_TOT * 4>>>(b1, g1, be1, w2, b2, g2, be2,
                                     hw1, hb1, hg1, hbe1, hw2, hb2, out);
}

// round 17
// speedup vs baseline: 1.2183x; 1.0056x over previous
#include <cuda_runtime.h>
#include <cuda_fp16.h>
#include <cstdint>
#include <cstddef>

#define BR    4096
#define MF    20000
#define EMB   100
#define WROWS 104
#define KC    32
#define KSPL  4
#define EPSB  1e-5f
#define STG   22528         // A(p0) 4K | A(p1) 4K | Wh 7K | Wl 7K
#define NSTG  4
#define WSC   64.0f

typedef unsigned long long u64;
typedef unsigned int u32;

// ---------------- device scratch ----------------
__device__ int   g_mode;
__device__ unsigned short g_Wh[WROWS * MF];
__device__ unsigned short g_Wl[WROWS * MF];
__device__ float g_Part[KSPL][2][BR][104];
__device__ float g_P[3][2][128][2][EMB];       // stage, pass, tile32, {sum,sumsq}, col
__device__ float g_scb[3][2][2][EMB];          // stage, pass, {scale,shift}, col
__device__ int   g_cnt[3];
__device__ int   g_flag[3];

// ---------------- helpers ----------------
__device__ __forceinline__ u32 smem_u32(const void* p) {
    u32 a; asm("{ .reg .u64 t; cvta.to.shared.u64 t, %1; cvt.u32.u64 %0, t; }" : "=r"(a) : "l"(p));
    return a;
}
__device__ __forceinline__ void ldsm4(u32& r0, u32& r1, u32& r2, u32& r3, u32 addr) {
    asm volatile("ldmatrix.sync.aligned.m8n8.x4.shared.b16 {%0,%1,%2,%3}, [%4];"
        : "=r"(r0), "=r"(r1), "=r"(r2), "=r"(r3) : "r"(addr));
}
__device__ __forceinline__ void mma16816(float* d, const u32* a, const u32* b) {
    asm volatile("mma.sync.aligned.m16n8k16.row.col.f32.f16.f16.f32 "
        "{%0,%1,%2,%3}, {%4,%5,%6,%7}, {%8,%9}, {%0,%1,%2,%3};"
        : "+f"(d[0]), "+f"(d[1]), "+f"(d[2]), "+f"(d[3])
        : "r"(a[0]), "r"(a[1]), "r"(a[2]), "r"(a[3]), "r"(b[0]), "r"(b[1]));
}
__device__ __forceinline__ void cp16(u32 dst, const void* src) {
    asm volatile("cp.async.cg.shared.global [%0], [%1], 16;"
        :: "r"(dst), "l"(src) : "memory");
}
#define CP_COMMIT() asm volatile("cp.async.commit_group;" ::: "memory")
#define CP_WAIT1()  asm volatile("cp.async.wait_group 1;" ::: "memory")

__device__ __forceinline__ u32 sw64(u32 row, u32 colb) {
    return row * 64 + (colb ^ (((row >> 1) & 3) << 4));
}
__device__ __forceinline__ u32 pk_f16(float lo, float hi) {
    u32 r; asm("cvt.rn.f16x2.f32 %0, %1, %2;" : "=r"(r) : "f"(hi), "f"(lo));
    return r;
}
__device__ __forceinline__ u64 pk2(float lo, float hi) {
    u64 d; asm("mov.b64 %0, {%1, %2};" : "=l"(d) : "f"(lo), "f"(hi)); return d;
}
__device__ __forceinline__ u64 fma2(u64 a, u64 b, u64 c) {
    u64 d; asm("fma.rn.f32x2 %0, %1, %2, %3;" : "=l"(d) : "l"(a), "l"(b), "l"(c)); return d;
}
__device__ __forceinline__ float2 upk2(u64 v) {
    float2 r; asm("mov.b64 {%0, %1}, %2;" : "=f"(r.x), "=f"(r.y) : "l"(v)); return r;
}

// ---------------- W split precompute + (block 0, first launch) detect ------
__global__ void k_prep(const float* __restrict__ w, int base,
                       const unsigned char* __restrict__ m, int do_detect)
{
    if (do_detect && blockIdx.x == 0) {
        __shared__ int s_nz, s_gt;
        if (threadIdx.x < 3) { g_cnt[threadIdx.x] = 0; g_flag[threadIdx.x] = 0; }
        if (threadIdx.x == 0) { s_nz = 0; s_gt = 0; }
        __syncthreads();
        int nz = 0, gt = 0;
        for (int i = threadIdx.x; i < 65536; i += blockDim.x) {
            unsigned char v = m[i];
            nz += (v != 0); gt += (v > 1);
        }
        atomicAdd(&s_nz, nz); atomicAdd(&s_gt, gt);
        __syncthreads();
        if (threadIdx.x == 0)
            g_mode = (s_gt > 64) ? 2 : (s_nz > 24576) ? 1 : 0;
    }
    int i = base + blockIdx.x * blockDim.x + threadIdx.x;
    if (i >= WROWS * MF / 2) return;
    int row = i / (MF / 2), within = i % (MF / 2);
    if (row < EMB) {
        float2 v = *(const float2*)(w + (size_t)row * MF + 2 * within);
        float sx = WSC * v.x, sy = WSC * v.y;
        float hx = __half2float(__float2half_rn(sx));
        float hy = __half2float(__float2half_rn(sy));
        ((u32*)g_Wh)[i] = pk_f16(hx, hy);
        ((u32*)g_Wl)[i] = pk_f16(sx - hx, sy - hy);
    } else {
        ((u32*)g_Wh)[i] = 0u;
        ((u32*)g_Wl)[i] = 0u;
    }
}

// ---------------- Layer 1: 2-term fp16 mma.sync (R13 verbatim) -------------
__global__ __launch_bounds__(256, 2)
void k_big(const float* __restrict__ x, const void* __restrict__ mk,
           const float* __restrict__ xr)
{
    extern __shared__ char smem[];
    const u32 sb = smem_u32(smem);
    const int t = threadIdx.x;
    const int w = t >> 5, lane = t & 31;
    const int tile = blockIdx.x >> 2, ks = blockIdx.x & 3;
    const int r0g = tile * 64;
    const int ci0 = ks ? (157 + 156 * (ks - 1)) : 0;
    const int n   = ks ? 156 : 157;
    const size_t k0g = (size_t)ci0 * KC;
    const int pa = w >> 2, nc = w & 3;
    const int mode = g_mode;

    const int arow = t >> 2, seg = t & 3;
    const size_t abase = (size_t)(r0g + arow) * MF + k0g + (size_t)seg * 8;
    const u32 aoff = sw64(arow, seg * 16);

    const int gi1 = t + 256;
    const bool w1v = (gi1 < 416);
    const int wr0 = t >> 2, wsg0 = t & 3;
    const int wr1 = gi1 >> 2, wsg1 = gi1 & 3;
    const u32 woff0 = sw64(wr0, wsg0 * 16);
    const u32 woff1 = sw64(wr1, wsg1 * 16);
    const size_t wsrc0 = (size_t)wr0 * MF + k0g + (size_t)wsg0 * 8;
    const size_t wsrc1 = (size_t)wr1 * MF + k0g + (size_t)wsg1 * 8;

    float acc[4][4][4];
    #pragma unroll
    for (int mf = 0; mf < 4; mf++)
        #pragma unroll
        for (int nf = 0; nf < 4; nf++)
            #pragma unroll
            for (int e = 0; e < 4; e++) acc[mf][nf][e] = 0.f;

    {
        const int stg_i = t >> 6, rem = t & 63;
        const int mat = rem >> 5, rr = 104 + ((rem & 31) >> 2), s = rem & 3;
        *(uint4*)(smem + stg_i * STG + 8192 + mat * 7168 + sw64(rr, s * 16)) =
            make_uint4(0, 0, 0, 0);
    }

    auto CPW = [&](int j) {
        const u32 base = sb + (j & 3) * STG;
        const size_t ko = (size_t)j * KC;
        cp16(base +  8192 + woff0, g_Wh + wsrc0 + ko);
        cp16(base + 15360 + woff0, g_Wl + wsrc0 + ko);
        if (w1v) {
            cp16(base +  8192 + woff1, g_Wh + wsrc1 + ko);
            cp16(base + 15360 + woff1, g_Wl + wsrc1 + ko);
        }
    };

    auto STAGE = [&](int j) {
        const size_t g = abase + (size_t)j * KC;
        float v[8], vc[8];
        float4 x0 = *(const float4*)(x + g);
        float4 x1 = *(const float4*)(x + g + 4);
        v[0]=x0.x; v[1]=x0.y; v[2]=x0.z; v[3]=x0.w;
        v[4]=x1.x; v[5]=x1.y; v[6]=x1.z; v[7]=x1.w;
        float4 q0 = *(const float4*)(xr + g);
        float4 q1 = *(const float4*)(xr + g + 4);
        float q[8] = {q0.x,q0.y,q0.z,q0.w,q1.x,q1.y,q1.z,q1.w};
        if (mode == 1) {
            uint2 mm = *(const uint2*)((const unsigned char*)mk + g);
            u32 lo = mm.x, hi = mm.y;
            #pragma unroll
            for (int m = 0; m < 4; m++) {
                vc[m]   = ((lo >> (m*8)) & 0xff) ? q[m]   : v[m];
                vc[m+4] = ((hi >> (m*8)) & 0xff) ? q[m+4] : v[m+4];
            }
        } else if (mode == 0) {
            int4 m0 = *(const int4*)((const int*)mk + g);
            int4 m1 = *(const int4*)((const int*)mk + g + 4);
            int mi[8] = {m0.x,m0.y,m0.z,m0.w,m1.x,m1.y,m1.z,m1.w};
            #pragma unroll
            for (int m = 0; m < 8; m++) vc[m] = mi[m] ? q[m] : v[m];
        } else {
            float4 m0 = *(const float4*)((const float*)mk + g);
            float4 m1 = *(const float4*)((const float*)mk + g + 4);
            float mf_[8] = {m0.x,m0.y,m0.z,m0.w,m1.x,m1.y,m1.z,m1.w};
            #pragma unroll
            for (int m = 0; m < 8; m++) vc[m] = (mf_[m] != 0.f) ? q[m] : v[m];
        }
        uint4 HA0, HA1;
        HA0.x = pk_f16(v[0],v[1]);  HA0.y = pk_f16(v[2],v[3]);
        HA0.z = pk_f16(v[4],v[5]);  HA0.w = pk_f16(v[6],v[7]);
        HA1.x = pk_f16(vc[0],vc[1]); HA1.y = pk_f16(vc[2],vc[3]);
        HA1.z = pk_f16(vc[4],vc[5]); HA1.w = pk_f16(vc[6],vc[7]);
        char* bs = smem + (j & 3) * STG;
        *(uint4*)(bs +        aoff) = HA0;
        *(uint4*)(bs + 4096 + aoff) = HA1;
    };

    const u32 rA0 = lane & 15;
    const u32 c16A = ((lane >> 4) & 1) * 16;
    const u32 xrA0 = ((rA0 >> 1) & 3) << 4;
    const u32 nrow = nc * 32 + ((lane >> 4) & 1) * 8 + (lane & 7);
    const u32 c16B = ((lane >> 3) & 1) * 16;
    const u32 baseB0 = nrow * 64,        xrB0 = ((nrow >> 1) & 3) << 4;
    const u32 baseB1 = (nrow + 16) * 64, xrB1 = (((nrow + 16) >> 1) & 3) << 4;

    auto COMP = [&](int j) {
        const u32 bs = sb + (j & 3) * STG;
        const u32 Ab = bs + pa * 4096;
        const u32 Wh = bs + 8192, Wl = bs + 15360;
        #pragma unroll
        for (int kss = 0; kss < 2; kss++) {
            const u32 kb = kss * 32;
            const u32 ka = (kb + c16A) ^ xrA0;
            u32 aF[4][4];
            #pragma unroll
            for (int mf = 0; mf < 4; mf++)
                ldsm4(aF[mf][0], aF[mf][1], aF[mf][2], aF[mf][3],
                      Ab + rA0 * 64 + mf * 1024 + ka);
            if (nc < 3) {
                u32 bH[4][2], bL[4][2];
                ldsm4(bH[0][0], bH[0][1], bH[1][0], bH[1][1], Wh + baseB0 + ((kb + c16B) ^ xrB0));
                ldsm4(bH[2][0], bH[2][1], bH[3][0], bH[3][1], Wh + baseB1 + ((kb + c16B) ^ xrB1));
                ldsm4(bL[0][0], bL[0][1], bL[1][0], bL[1][1], Wl + baseB0 + ((kb + c16B) ^ xrB0));
                ldsm4(bL[2][0], bL[2][1], bL[3][0], bL[3][1], Wl + baseB1 + ((kb + c16B) ^ xrB1));
                #pragma unroll
                for (int mf = 0; mf < 4; mf++)
                    #pragma unroll
                    for (int nf = 0; nf < 4; nf++) {
                        mma16816(acc[mf][nf], aF[mf], bH[nf]);
                        mma16816(acc[mf][nf], aF[mf], bL[nf]);
                    }
            } else {
                u32 bH[2][2], bL[2][2];
                ldsm4(bH[0][0], bH[0][1], bH[1][0], bH[1][1], Wh + baseB0 + ((kb + c16B) ^ xrB0));
                ldsm4(bL[0][0], bL[0][1], bL[1][0], bL[1][1], Wl + baseB0 + ((kb + c16B) ^ xrB0));
                #pragma unroll
                for (int mf = 0; mf < 4; mf++)
                    #pragma unroll
                    for (int nf = 0; nf < 2; nf++) {
                        mma16816(acc[mf][nf], aF[mf], bH[nf]);
                        mma16816(acc[mf][nf], aF[mf], bL[nf]);
                    }
            }
        }
    };

    CPW(0); CP_COMMIT();
    CPW(1); CP_COMMIT();
    CPW(2); CP_COMMIT();
    STAGE(0);
    STAGE(1);
    CP_WAIT1();
    __syncthreads();

    int i = 0;
    for (; i + 1 < n; i += 2) {
        COMP(i);
        if (i + 2 < n) STAGE(i + 2);
        COMP(i + 1);
        if (i + 3 < n) STAGE(i + 3);
        if (i + 3 < n) CPW(i + 3);
        CP_COMMIT();
        if (i + 4 < n) CPW(i + 4);
        CP_COMMIT();
        CP_WAIT1();
        __syncthreads();
    }
    if (i < n) COMP(i);

    float* Pp = &g_Part[ks][pa][0][0];
    const int gq = lane >> 2, tt = lane & 3;
    #pragma unroll
    for (int mf = 0; mf < 4; mf++)
        #pragma unroll
        for (int nf = 0; nf < 4; nf++) {
            const int col = nc * 32 + nf * 8 + 2 * tt;
            if (col < EMB) {
                const int ra = r0g + mf * 16 + gq;
                *(float2*)&Pp[(size_t)ra * 104 + col] =
                    make_float2(acc[mf][nf][0], acc[mf][nf][1]);
                *(float2*)&Pp[(size_t)(ra + 8) * 104 + col] =
                    make_float2(acc[mf][nf][2], acc[mf][nf][3]);
            }
        }
}

// ---------------- persistent tail v2 (profiled this round) -----------------
#define T_HS  0
#define T_HB  3300
#define T_WS  6600
#define T_RED 19800
#define T_SC  21848
#define T_SH  21976
#define T_TOT 22104

__device__ __forceinline__ void tail_bar(int ph, int stage,
    const float* gamma, const float* beta, int t)
{
    __shared__ int s_old;
    __threadfence();
    if (t == 0) s_old = atomicAdd(&g_cnt[ph], 1);
    __syncthreads();
    if (s_old == 255) {
        if (t < 200) {
            const int pp = t / 100, c = t % 100;
            float s = 0.f, s2 = 0.f;
            #pragma unroll 8
            for (int it = 0; it < 128; it++) {
                s  += g_P[stage][pp][it][0][c];
                s2 += g_P[stage][pp][it][1][c];
            }
            float mu  = s * (1.f / BR);
            float var = s2 * (1.f / BR) - mu * mu;
            float sv  = gamma[c] * rsqrtf(var + EPSB);
            g_scb[stage][pp][0][c] = sv;
            g_scb[stage][pp][1][c] = beta[c] - mu * sv;
        }
        __syncthreads();
        __threadfence();
        if (t == 0) atomicExch(&g_flag[ph], 1);
    } else {
        if (t == 0) {
            volatile int* f = &g_flag[ph];     // plain-load poll (no RMW serialize)
            while (*f == 0) __nanosleep(128);
        }
        __syncthreads();
    }
}

__device__ __forceinline__ void w_fetch(const float* __restrict__ W, uint4* wr, int t) {
    #pragma unroll
    for (int j = 0; j < 10; j++) {
        int f = t + 256 * j;
        wr[j] = (f < 2500) ? *(const uint4*)(W + 4 * f) : make_uint4(0, 0, 0, 0);
    }
}
__device__ __forceinline__ void w_unpack(float* Ws, const uint4* wr, int t) {
    #pragma unroll
    for (int j = 0; j < 10; j++) {
        int f = t + 256 * j;
        if (f < 2500) {
            int nn = f / 25, kq = (f % 25) * 4;
            Ws[(kq    ) * 132 + nn] = __uint_as_float(wr[j].x);
            Ws[(kq + 1) * 132 + nn] = __uint_as_float(wr[j].y);
            Ws[(kq + 2) * 132 + nn] = __uint_as_float(wr[j].z);
            Ws[(kq + 3) * 132 + nn] = __uint_as_float(wr[j].w);
        }
    }
}

__device__ void tail_gemm(float* sm, const float* __restrict__ bias,
                          bool rout, int outstage, int p, int tile,
                          float* __restrict__ out, int t)
{
    float* Hb = sm + T_HB;
    float* Ws = sm + T_WS;
    float* red = sm + T_RED;
    const int ty = t >> 4, tx = t & 15;

    u64 acc[2][4];
    #pragma unroll
    for (int r = 0; r < 2; r++)
        #pragma unroll
        for (int c = 0; c < 4; c++) acc[r][c] = 0ull;

    #pragma unroll 4
    for (int k = 0; k < EMB; k++) {
        const float* ak = Hb + k * 33 + ty * 2;
        float a0 = ak[0], a1 = ak[1];
        const u64* wp = (const u64*)(Ws + k * 132 + tx * 8);
        u64 b0 = wp[0], b1 = wp[1], b2 = wp[2], b3 = wp[3];
        u64 A0 = pk2(a0, a0), A1 = pk2(a1, a1);
        acc[0][0]=fma2(A0,b0,acc[0][0]); acc[0][1]=fma2(A0,b1,acc[0][1]);
        acc[0][2]=fma2(A0,b2,acc[0][2]); acc[0][3]=fma2(A0,b3,acc[0][3]);
        acc[1][0]=fma2(A1,b0,acc[1][0]); acc[1][1]=fma2(A1,b1,acc[1][1]);
        acc[1][2]=fma2(A1,b2,acc[1][2]); acc[1][3]=fma2(A1,b3,acc[1][3]);
    }

    float* Hs = sm + T_HS;
    float vo[2][8];
    #pragma unroll
    for (int r = 0; r < 2; r++) {
        const int row_l = ty * 2 + r;
        #pragma unroll
        for (int cp = 0; cp < 4; cp++) {
            float2 f = upk2(acc[r][cp]);
            #pragma unroll
            for (int hh = 0; hh < 2; hh++) {
                int col = tx * 8 + cp * 2 + hh;
                float v = (hh ? f.y : f.x) + (col < EMB ? bias[col] : 0.f);
                if (rout) v = fmaxf(v, 0.f);
                vo[r][cp * 2 + hh] = v;
                if (col < EMB) {
                    if (out) out[((size_t)p * BR + tile * 32 + row_l) * EMB + col] = v;
                    else     Hs[col * 33 + row_l] = v;
                }
            }
        }
    }
    if (outstage >= 0) {
        __syncthreads();
        #pragma unroll
        for (int c = 0; c < 8; c++)
            red[ty * 128 + tx * 8 + c] = vo[0][c] + vo[1][c];
        __syncthreads();
        if (t < 128) {
            float s = 0.f;
            #pragma unroll
            for (int g = 0; g < 16; g++) s += red[g * 128 + t];
            if (t < EMB) g_P[outstage][p][tile][0][t] = s;
        }
        __syncthreads();
        #pragma unroll
        for (int c = 0; c < 8; c++)
            red[ty * 128 + tx * 8 + c] = vo[0][c]*vo[0][c] + vo[1][c]*vo[1][c];
        __syncthreads();
        if (t < 128) {
            float s = 0.f;
            #pragma unroll
            for (int g = 0; g < 16; g++) s += red[g * 128 + t];
            if (t < EMB) g_P[outstage][p][tile][1][t] = s;
        }
    }
    __syncthreads();
}

__device__ __forceinline__ void bn_apply(float* sm, bool rin, int t) {
    float* Hs = sm + T_HS;
    float* Hb = sm + T_HB;
    float* sc = sm + T_SC;
    float* sh = sm + T_SH;
    #pragma unroll
    for (int j = 0; j < 13; j++) {
        int i = t + 256 * j;
        if (i < 3300) {
            int k = i / 33;
            float v = Hs[i] * sc[k] + sh[k];
            if (rin) v = fmaxf(v, 0.f);
            Hb[i] = v;
        }
    }
    __syncthreads();
}
__device__ __forceinline__ void scb_load(float* sm, int stage, int p, int t) {
    if (t < EMB) {
        sm[T_SC + t] = g_scb[stage][p][0][t];
        sm[T_SH + t] = g_scb[stage][p][1][t];
    }
}

__global__ __launch_bounds__(256, 2)
void k_tail2(const float* __restrict__ b1,
             const float* __restrict__ g1,  const float* __restrict__ be1,
             const float* __restrict__ w2,  const float* __restrict__ b2,
             const float* __restrict__ g2,  const float* __restrict__ be2,
             const float* __restrict__ hw1, const float* __restrict__ hb1,
             const float* __restrict__ hg1, const float* __restrict__ hbe1,
             const float* __restrict__ hw2, const float* __restrict__ hb2,
             float* __restrict__ out)
{
    extern __shared__ float sm[];
    const int t = threadIdx.x;
    const int p = blockIdx.x >> 7, tile = blockIdx.x & 127;
    const int r0 = tile * 32;
    float* Hs = sm + T_HS;
    float* Ws = sm + T_WS;
    uint4 wreg[10];

    for (int i = t; i < 2800; i += 256) {
        int k = i / 28, nn = 100 + i % 28;
        Ws[k * 132 + nn] = 0.f;
    }

    w_fetch(w2, wreg, t);

    // ---- phase 0: merge K-splits -> Hs + stage-0 partials ----
    {
        #pragma unroll
        for (int j = 0; j < 4; j++) {
            int f = t + 256 * j;
            if (f < 832) {
                int row = f / 26, cq = (f % 26) * 4;
                const float* P0 = &g_Part[0][p][r0 + row][cq];
                const float* P1 = &g_Part[1][p][r0 + row][cq];
                const float* P2 = &g_Part[2][p][r0 + row][cq];
                const float* P3 = &g_Part[3][p][r0 + row][cq];
                float4 a = *(const float4*)P0, b = *(const float4*)P1;
                float4 c = *(const float4*)P2, d = *(const float4*)P3;
                float v[4] = { a.x+b.x+c.x+d.x, a.y+b.y+c.y+d.y,
                               a.z+b.z+c.z+d.z, a.w+b.w+c.w+d.w };
                #pragma unroll
                for (int e = 0; e < 4; e++) {
                    int cc = cq + e;
                    if (cc < EMB) {
                        float u = fmaxf(v[e] * (1.0f / WSC) + b1[cc], 0.f);
                        Hs[cc * 33 + row] = u;
                    }
                }
            }
        }
        __syncthreads();
        if (t < EMB) {
            float s = 0.f, s2 = 0.f;
            #pragma unroll 8
            for (int r = 0; r < 32; r++) { float u = Hs[t * 33 + r]; s += u; s2 += u * u; }
            g_P[0][p][tile][0][t] = s;
            g_P[0][p][tile][1][t] = s2;
        }
        __syncthreads();
    }
    tail_bar(0, 0, g1, be1, t);

    // ---- phase 1: enc layer 2 (BN0 in, relu out) ----
    w_unpack(Ws, wreg, t);
    scb_load(sm, 0, p, t);
    __syncthreads();
    bn_apply(sm, false, t);
    tail_gemm(sm, b2, true, 1, p, tile, nullptr, t);
    w_fetch(hw1, wreg, t);
    tail_bar(1, 1, g2, be2, t);

    // ---- phase 2: head layer 1 (BN1 in, no relu) ----
    w_unpack(Ws, wreg, t);
    scb_load(sm, 1, p, t);
    __syncthreads();
    bn_apply(sm, false, t);
    tail_gemm(sm, hb1, false, 2, p, tile, nullptr, t);
    w_fetch(hw2, wreg, t);
    tail_bar(2, 2, hg1, hbe1, t);

    // ---- phase 3: head layer 2 (relu(BN2) in) -> out ----
    w_unpack(Ws, wreg, t);
    scb_load(sm, 2, p, t);
    __syncthreads();
    bn_apply(sm, true, t);
    tail_gemm(sm, hb2, false, -1, p, tile, out, t);
}

// ---------------- launch ----------------
extern "C" void kernel_launch(void* const* d_in, const int* in_sizes, int n_in,
                              void* d_out, int out_size)
{
    const float* x   = (const float*)d_in[0];
    const void*  mk  = d_in[1];
    const float* xr  = (const float*)d_in[2];
    const float* w1  = (const float*)d_in[3];
    const float* b1  = (const float*)d_in[4];
    const float* g1  = (const float*)d_in[5];
    const float* be1 = (const float*)d_in[6];
    const float* w2  = (const float*)d_in[7];
    const float* b2  = (const float*)d_in[8];
    const float* g2  = (const float*)d_in[9];
    const float* be2 = (const float*)d_in[10];
    const float* hw1 = (const float*)d_in[11];
    const float* hb1 = (const float*)d_in[12];
    const float* hg1 = (const float*)d_in[13];
    const float* hbe1= (const float*)d_in[14];
    const float* hw2 = (const float*)d_in[15];
    const float* hb2 = (const float*)d_in[16];
    float* out = (float*)d_out;

    cudaFuncSetAttribute(k_big,   cudaFuncAttributeMaxDynamicSharedMemorySize, NSTG * STG);
    cudaFuncSetAttribute(k_tail2, cudaFuncAttributeMaxDynamicSharedMemorySize, T_TOT * 4);

    const int H = WROWS * MF / 2 / 2;
    k_prep<<<(H + 255) / 256, 256>>>(w1, 0, (const unsigned char*)mk, 1);  // 1
    k_prep<<<(H + 255) / 256, 256>>>(w1, H, (const unsigned char*)mk, 0);  // 2
    k_big<<<256, 256, NSTG * STG>>>(x, mk, xr);                            // 3
    k_tail2<<<256, 256, T_TOT * 4>>>(b1, g1, be1, w2, b2, g2, be2,         // 4 <- profiled
                                     hw1, hb1, hg1, hbe1, hw2, hb2, out);
}